// round 9
// baseline (speedup 1.0000x reference)
#include <cuda_runtime.h>
#include <cuda_fp16.h>
#include <cstdint>
#include <cstddef>

// ---------------- problem constants ----------------
#define Bb   4
#define Np   16384
#define Cf   128
#define Mq   1024
#define Kq   32
#define NNc  131072            // Bb*Mq*Kq (GEMM column count)
#define R2c  0.16f
#define EPSv 1e-5f
#define KCP1 160               // layer1 K padded (131 -> 160 = 5 chunks of 32)
#define NCTA 1024
#define NQ   4096              // total queries (B*M)

// ---------------- scratch (device globals) ----------------
__device__ int   g_idx[NNc];
__device__ __align__(16) __half g_Whf[KCP1*128 + 128*128 + 128*256];  // fp16 W, [o][cpad]
__device__ float g_featT[(size_t)Bb * Np * Cf];        // 32 MB
__device__ float g_Y1[(size_t)128 * NNc];              // 64 MB
__device__ float g_Y2[(size_t)128 * NNc];              // 64 MB
__device__ float g_mx[(size_t)256 * NQ];               // 4 MB  (layer3 raw max over K)
__device__ float g_ps[256 * NCTA];
__device__ float g_pq[256 * NCTA];
__device__ float g_scale[256];
__device__ float g_shift[256];

// ---------------- helpers ----------------
__device__ __forceinline__ uint32_t smem_u32(const void* p) {
    uint32_t a;
    asm("{ .reg .u64 t; cvta.to.shared.u64 t, %1; cvt.u32.u64 %0, t; }" : "=r"(a) : "l"(p));
    return a;
}
// pack two floats into f16x2 (lo, hi)
__device__ __forceinline__ uint32_t f22h(float lo, float hi) {
    uint32_t r;
    asm("cvt.rn.f16x2.f32 %0, %1, %2;" : "=r"(r) : "f"(hi), "f"(lo));
    return r;
}
#define CPASYNC16(dst, src) \
    asm volatile("cp.async.ca.shared.global [%0],[%1],16;" :: "r"(dst), "l"(src))
#define LDSM_X4(d0,d1,d2,d3,a) \
    asm volatile("ldmatrix.sync.aligned.m8n8.x4.shared.b16 {%0,%1,%2,%3},[%4];" \
                 : "=r"(d0),"=r"(d1),"=r"(d2),"=r"(d3) : "r"(a))
#define LDSM_X2(d0,d1,a) \
    asm volatile("ldmatrix.sync.aligned.m8n8.x2.shared.b16 {%0,%1},[%2];" \
                 : "=r"(d0),"=r"(d1) : "r"(a))
#define MMA16816(c, a, b) \
    asm volatile("mma.sync.aligned.m16n8k16.row.col.f32.f16.f16.f32 " \
                 "{%0,%1,%2,%3},{%4,%5,%6,%7},{%8,%9},{%0,%1,%2,%3};" \
                 : "+f"((c)[0]),"+f"((c)[1]),"+f"((c)[2]),"+f"((c)[3]) \
                 : "r"((a)[0]),"r"((a)[1]),"r"((a)[2]),"r"((a)[3]), \
                   "r"((b)[0]),"r"((b)[1]))

// ---------------- kernel: gather new_xyz ----------------
__global__ void k_newxyz(const float* __restrict__ pxyz, const int* __restrict__ ind,
                         float* __restrict__ out)
{
    int i = blockIdx.x * blockDim.x + threadIdx.x;
    if (i >= Bb * Mq) return;
    int b = i >> 10;
    int n = ind[i];
    const float* p = pxyz + ((size_t)b * Np + n) * 3;
    out[i * 3 + 0] = p[0];
    out[i * 3 + 1] = p[1];
    out[i * 3 + 2] = p[2];
}

// ---------------- kernel: ball query (warp per query) ----------------
__global__ void k_ballquery(const float* __restrict__ pxyz, const float* __restrict__ nxyz)
{
    int gtid = blockIdx.x * blockDim.x + threadIdx.x;
    int q    = gtid >> 5;
    int lane = gtid & 31;
    int b    = q >> 10;

    float nx = nxyz[q * 3 + 0], ny = nxyz[q * 3 + 1], nz = nxyz[q * 3 + 2];
    const float* px = pxyz + (size_t)b * Np * 3;

    int cnt = 0, first = 0;
    for (int n0 = 0; n0 < Np; n0 += 32) {
        int n = n0 + lane;
        float dx = px[n * 3 + 0] - nx, dy = px[n * 3 + 1] - ny, dz = px[n * 3 + 2] - nz;
        float d2 = __fadd_rn(__fadd_rn(__fmul_rn(dx, dx), __fmul_rn(dy, dy)), __fmul_rn(dz, dz));
        bool within = d2 < R2c;
        unsigned bal = __ballot_sync(0xffffffffu, within);
        if (bal) {
            if (cnt == 0) first = n0 + __ffs(bal) - 1;
            int pre = __popc(bal & ((1u << lane) - 1u));
            if (within && (cnt + pre) < Kq) g_idx[q * Kq + cnt + pre] = n;
            cnt += __popc(bal);
            if (cnt >= Kq) break;
        }
    }
    cnt = min(cnt, Kq);
    if (lane >= cnt) g_idx[q * Kq + lane] = first;
}

// ---------------- kernel: transpose features -> featT[b][n][c] ----------------
__global__ void k_transpose(const float* __restrict__ f, float* __restrict__ ft)
{
    __shared__ float t[32][33];
    int b  = blockIdx.z;
    int n0 = blockIdx.x << 5, c0 = blockIdx.y << 5;
    int tx = threadIdx.x, ty = threadIdx.y;       // 32 x 8
#pragma unroll
    for (int i = 0; i < 32; i += 8)
        t[ty + i][tx] = f[((size_t)b * Cf + c0 + ty + i) * Np + n0 + tx];
    __syncthreads();
#pragma unroll
    for (int i = 0; i < 32; i += 8)
        ft[((size_t)b * Np + n0 + ty + i) * Cf + c0 + tx] = t[tx][ty + i];
}

// ---------------- kernel: pack layer-1 weights -> fp16 [o][cpad] (permuted) ----------------
__global__ void k_packW1(const float* __restrict__ W, __half* __restrict__ Wh)
{
    int o = blockIdx.x, c = threadIdx.x;
    if (c >= KCP1) return;
    float v = 0.f;
    // packed channel order: 0..127 = feat (orig 3..130), 128..130 = xyz (orig 0..2)
    int oc = (c < 128) ? (c + 3) : ((c < 131) ? (c - 128) : -1);
    if (oc >= 0) v = W[o * 131 + oc];
    Wh[o * KCP1 + c] = __float2half_rn(v);
}

// ---------------- kernel: pack w2+w3 (merged launch) ----------------
__global__ void k_packW23(const float* __restrict__ W2, const float* __restrict__ W3,
                          __half* __restrict__ Wh2, __half* __restrict__ Wh3)
{
    int blk = blockIdx.x, c = threadIdx.x;       // 128 threads
    if (blk < 128) {
        Wh2[blk * 128 + c] = __float2half_rn(W2[blk * 128 + c]);
    } else {
        int o = blk - 128;                        // 0..255
        Wh3[o * 128 + c] = __float2half_rn(W3[o * 128 + c]);
    }
}

// ---------------- fused fp16 GEMM (double-buffered, ldmatrix + m16n8k16) ----------------
// Y[o][n] = sum_c W[o][c] * X[n][c] + bias[o]; per-CTA channel partial stats.
// CTA tile 128(M) x 128(N), K-chunk 32; 8 warps 2(M)x4(N), warp tile 64x32.
// MODE 0: B generated by gather/concat on the fly (layer 1)
// MODE 1: B = relu(scale*Yprev + shift) (layers 2/3)
// DOMAX 1: no Y write; per-(row, query) max of accumulators -> g_mx.
#define SSTR 40                   // smem row stride in halves (80B, ldmatrix conflict-free)
#define ABUF (128 * SSTR)         // one A buffer in halves (5120)
template <int MODE, int DOMAX>
__global__ void __launch_bounds__(256) k_gemm_h(
    const __half* __restrict__ Wh, const float* __restrict__ bias,
    int kchunks, int KCpad,
    const float* __restrict__ Bsrc,
    const float* __restrict__ pxyz, const float* __restrict__ nxyz,
    float* __restrict__ Y)
{
    extern __shared__ __half dsm[];   // [A buf0][A buf1][B buf0][B buf1], each ABUF halves
    __shared__ float s_sum[128], s_sq[128];

    const int tid  = threadIdx.x;
    const int wid  = tid >> 5, lane = tid & 31;
    const int n0   = blockIdx.x << 7;
    const int o0   = blockIdx.y << 7;
    const int wm   = wid >> 2;
    const int wn   = wid & 3;

    if (tid < 128) { s_sum[tid] = 0.f; s_sq[tid] = 0.f; }

    float acc[4][4][4];
#pragma unroll
    for (int mt = 0; mt < 4; mt++)
#pragma unroll
        for (int nt = 0; nt < 4; nt++)
#pragma unroll
            for (int r = 0; r < 4; r++) acc[mt][nt][r] = 0.f;

    uint32_t pv[8];   // staged B halves (4 iters x 2 f16x2)

#define STAGE_A(KT, BUF) do {                                                  \
    uint32_t base = smem_u32(dsm) + (BUF) * (ABUF * 2);                        \
    _Pragma("unroll")                                                          \
    for (int s = 0; s < 2; s++) {                                              \
        int idx = tid + (s << 8);            /* 0..511 */                      \
        int row = idx >> 2, seg = idx & 3;                                     \
        const __half* src = Wh + (size_t)(o0 + row) * KCpad + (KT) * 32 + seg * 8; \
        CPASYNC16(base + row * (SSTR * 2) + seg * 16, src);                    \
    } } while (0)

#define PREFETCH_B(KT) do {                                                    \
    _Pragma("unroll")                                                          \
    for (int s = 0; s < 4; s++) {                                              \
        int idx = tid + (s << 8);                                              \
        int c4 = idx >> 7, j = idx & 127;    /* c4: 0..7, j: col in tile */    \
        int cg0 = (KT) * 32 + c4 * 4;                                          \
        float f0, f1, f2, f3;                                                  \
        if (MODE == 1) {                                                       \
            int n = n0 + j;                                                    \
            float y0 = Bsrc[(size_t)(cg0 + 0) * NNc + n];                      \
            float y1 = Bsrc[(size_t)(cg0 + 1) * NNc + n];                      \
            float y2 = Bsrc[(size_t)(cg0 + 2) * NNc + n];                      \
            float y3 = Bsrc[(size_t)(cg0 + 3) * NNc + n];                      \
            f0 = fmaxf(fmaf(g_scale[cg0 + 0], y0, g_shift[cg0 + 0]), 0.f);     \
            f1 = fmaxf(fmaf(g_scale[cg0 + 1], y1, g_shift[cg0 + 1]), 0.f);     \
            f2 = fmaxf(fmaf(g_scale[cg0 + 2], y2, g_shift[cg0 + 2]), 0.f);     \
            f3 = fmaxf(fmaf(g_scale[cg0 + 3], y3, g_shift[cg0 + 3]), 0.f);     \
        } else {                                                               \
            int col = n0 + j;                                                  \
            int idxv = g_idx[col];                                             \
            int b = col >> 15;                                                 \
            if (cg0 + 3 < 128) {                                               \
                float4 f = *(const float4*)&g_featT[((size_t)b*Np+idxv)*Cf+cg0]; \
                f0 = f.x; f1 = f.y; f2 = f.z; f3 = f.w;                        \
            } else {                                                           \
                int q = col >> 5;                                              \
                float fv[4];                                                   \
                _Pragma("unroll")                                              \
                for (int i2 = 0; i2 < 4; i2++) {                               \
                    int cg = cg0 + i2;                                         \
                    float x = 0.f;                                             \
                    if (cg < 128)                                              \
                        x = g_featT[((size_t)b * Np + idxv) * Cf + cg];        \
                    else if (cg < 131)                                         \
                        x = pxyz[((size_t)b * Np + idxv) * 3 + cg - 128]       \
                          - nxyz[q * 3 + cg - 128];                            \
                    fv[i2] = x;                                                \
                }                                                              \
                f0 = fv[0]; f1 = fv[1]; f2 = fv[2]; f3 = fv[3];                \
            }                                                                  \
        }                                                                      \
        pv[s * 2 + 0] = f22h(f0, f1);                                          \
        pv[s * 2 + 1] = f22h(f2, f3);                                          \
    } } while (0)

#define STAGE_B(BUF) do {                                                      \
    __half* sBc = dsm + 2 * ABUF + (BUF) * ABUF;                               \
    _Pragma("unroll")                                                          \
    for (int s = 0; s < 4; s++) {                                              \
        int idx = tid + (s << 8);                                              \
        int c4 = idx >> 7, j = idx & 127;                                      \
        *(uint2*)&sBc[j * SSTR + c4 * 4] = make_uint2(pv[s*2+0], pv[s*2+1]);   \
    } } while (0)

    // ---------- prologue ----------
    PREFETCH_B(0);
    STAGE_A(0, 0);
    STAGE_B(0);
    asm volatile("cp.async.wait_all;" ::: "memory");
    __syncthreads();

    // ldmatrix lane addressing (byte offsets into a buffer)
    const uint32_t rowA = ((wm * 64 + (lane & 15)) * SSTR + (lane >> 4) * 8) * 2;
    const uint32_t rowB = ((wn * 32 + (lane & 7)) * SSTR + ((lane >> 3) & 1) * 8) * 2;

    // ---------- pipelined mainloop ----------
    for (int kt = 0; kt < kchunks; kt++) {
        const int cur = kt & 1, nxt = cur ^ 1;
        const bool more = (kt + 1 < kchunks);
        if (more) {
            STAGE_A(kt + 1, nxt);      // async into alternate buffer
            PREFETCH_B(kt + 1);        // LDG into regs, overlaps MMA below
        }

        const uint32_t bA = smem_u32(dsm) + cur * (ABUF * 2);
        const uint32_t bB = smem_u32(dsm) + (2 + cur) * (ABUF * 2);
#pragma unroll
        for (int ks = 0; ks < 2; ks++) {
            // load all B fragments first, then stream A per-mt (lower live regs)
            uint32_t bh[4][2];
#pragma unroll
            for (int nt = 0; nt < 4; nt++) {
                uint32_t off = rowB + nt * (8 * SSTR * 2) + ks * 32;
                LDSM_X2(bh[nt][0], bh[nt][1], bB + off);
            }
#pragma unroll
            for (int mt = 0; mt < 4; mt++) {
                uint32_t ah[4];
                uint32_t off = rowA + mt * (16 * SSTR * 2) + ks * 32;
                LDSM_X4(ah[0], ah[1], ah[2], ah[3], bA + off);
#pragma unroll
                for (int nt = 0; nt < 4; nt++)
                    MMA16816(acc[mt][nt], ah, bh[nt]);
            }
        }

        if (more) STAGE_B(nxt);
        asm volatile("cp.async.wait_all;" ::: "memory");
        __syncthreads();
    }

    // ---------- epilogue ----------
    const int qid = lane >> 2;
    const int qt  = lane & 3;
#pragma unroll
    for (int mt = 0; mt < 4; mt++) {
        int m1 = wm * 64 + mt * 16 + qid;
        int m2 = m1 + 8;
        float bb1 = bias[o0 + m1], bb2 = bias[o0 + m2];
        float s1 = 0.f, q1 = 0.f, s2 = 0.f, q2 = 0.f;
        float mx1 = -3.4e38f, mx2 = -3.4e38f;
#pragma unroll
        for (int nt = 0; nt < 4; nt++) {
            float v0 = acc[mt][nt][0] + bb1, v1 = acc[mt][nt][1] + bb1;
            float v2 = acc[mt][nt][2] + bb2, v3 = acc[mt][nt][3] + bb2;
            if (!DOMAX) {
                int n = n0 + wn * 32 + nt * 8 + qt * 2;
                *(float2*)&Y[(size_t)(o0 + m1) * NNc + n] = make_float2(v0, v1);
                *(float2*)&Y[(size_t)(o0 + m2) * NNc + n] = make_float2(v2, v3);
            } else {
                mx1 = fmaxf(mx1, fmaxf(v0, v1));
                mx2 = fmaxf(mx2, fmaxf(v2, v3));
            }
            s1 += v0 + v1; q1 += v0 * v0 + v1 * v1;
            s2 += v2 + v3; q2 += v2 * v2 + v3 * v3;
        }
        s1 += __shfl_xor_sync(0xffffffffu, s1, 1); s1 += __shfl_xor_sync(0xffffffffu, s1, 2);
        q1 += __shfl_xor_sync(0xffffffffu, q1, 1); q1 += __shfl_xor_sync(0xffffffffu, q1, 2);
        s2 += __shfl_xor_sync(0xffffffffu, s2, 1); s2 += __shfl_xor_sync(0xffffffffu, s2, 2);
        q2 += __shfl_xor_sync(0xffffffffu, q2, 1); q2 += __shfl_xor_sync(0xffffffffu, q2, 2);
        if (DOMAX) {
            mx1 = fmaxf(mx1, __shfl_xor_sync(0xffffffffu, mx1, 1));
            mx1 = fmaxf(mx1, __shfl_xor_sync(0xffffffffu, mx1, 2));
            mx2 = fmaxf(mx2, __shfl_xor_sync(0xffffffffu, mx2, 1));
            mx2 = fmaxf(mx2, __shfl_xor_sync(0xffffffffu, mx2, 2));
            if (qt == 0) {
                int qidx = blockIdx.x * 4 + wn;     // warp tile N=32 == one query
                g_mx[(size_t)(o0 + m1) * NQ + qidx] = mx1;
                g_mx[(size_t)(o0 + m2) * NQ + qidx] = mx2;
            }
        }
        if (qt == 0) {
            atomicAdd(&s_sum[m1], s1); atomicAdd(&s_sq[m1], q1);
            atomicAdd(&s_sum[m2], s2); atomicAdd(&s_sq[m2], q2);
        }
    }
    __syncthreads();
    if (tid < 128) {
        g_ps[(size_t)(o0 + tid) * NCTA + blockIdx.x] = s_sum[tid];
        g_pq[(size_t)(o0 + tid) * NCTA + blockIdx.x] = s_sq[tid];
    }
#undef STAGE_A
#undef PREFETCH_B
#undef STAGE_B
}

// ---------------- kernel: reduce partials -> BN scale/shift ----------------
__global__ void k_reduce(const float* __restrict__ gam, const float* __restrict__ bet)
{
    __shared__ float ss[256], sq[256];
    int c = blockIdx.x, t = threadIdx.x;
    float s = g_ps[(size_t)c * NCTA + t]       + g_ps[(size_t)c * NCTA + 256 + t]
            + g_ps[(size_t)c * NCTA + 512 + t] + g_ps[(size_t)c * NCTA + 768 + t];
    float q = g_pq[(size_t)c * NCTA + t]       + g_pq[(size_t)c * NCTA + 256 + t]
            + g_pq[(size_t)c * NCTA + 512 + t] + g_pq[(size_t)c * NCTA + 768 + t];
    ss[t] = s; sq[t] = q;
    __syncthreads();
    for (int st = 128; st > 0; st >>= 1) {
        if (t < st) { ss[t] += ss[t + st]; sq[t] += sq[t + st]; }
        __syncthreads();
    }
    if (t == 0) {
        float mean = ss[0] * (1.f / NNc);
        float var  = sq[0] * (1.f / NNc) - mean * mean;
        float rs   = rsqrtf(var + EPSv);
        float sc   = gam[c] * rs;
        g_scale[c] = sc;
        g_shift[c] = fmaf(-mean, sc, bet[c]);
    }
}

// ---------------- kernel: BN3+ReLU applied to per-query max ----------------
__global__ void k_final(float* __restrict__ outf)
{
    int i = blockIdx.x * blockDim.x + threadIdx.x;   // 1048576
    int m = i & (Mq - 1);
    int o = (i >> 10) & 255;
    int b = i >> 18;
    float v = g_mx[(size_t)o * NQ + b * Mq + m];
    outf[((size_t)b * 256 + o) * Mq + m] = fmaxf(fmaf(g_scale[o], v, g_shift[o]), 0.f);
}

// ---------------- host launcher ----------------
extern "C" void kernel_launch(void* const* d_in, const int* in_sizes, int n_in,
                              void* d_out, int out_size)
{
    const float* pxyz = (const float*)d_in[0];
    const float* feat = (const float*)d_in[1];
    const int*   ind  = (const int*)d_in[2];
    const float* w1 = (const float*)d_in[3];  const float* b1 = (const float*)d_in[4];
    const float* g1 = (const float*)d_in[5];  const float* be1 = (const float*)d_in[6];
    const float* w2 = (const float*)d_in[7];  const float* b2 = (const float*)d_in[8];
    const float* g2 = (const float*)d_in[9];  const float* be2 = (const float*)d_in[10];
    const float* w3 = (const float*)d_in[11]; const float* b3 = (const float*)d_in[12];
    const float* g3 = (const float*)d_in[13]; const float* be3 = (const float*)d_in[14];

    float* out  = (float*)d_out;
    float* nxyz = out;
    float* fout = out + Bb * Mq * 3;

    float *pY1, *pY2, *pFT;
    __half* pWh;
    cudaGetSymbolAddress((void**)&pY1, g_Y1);
    cudaGetSymbolAddress((void**)&pY2, g_Y2);
    cudaGetSymbolAddress((void**)&pFT, g_featT);
    cudaGetSymbolAddress((void**)&pWh, g_Whf);

    const int DSM = 4 * ABUF * 2;   // 40960 bytes (A x2 + B x2, fp16)
    cudaFuncSetAttribute(k_gemm_h<0,0>, cudaFuncAttributeMaxDynamicSharedMemorySize, DSM);
    cudaFuncSetAttribute(k_gemm_h<1,0>, cudaFuncAttributeMaxDynamicSharedMemorySize, DSM);
    cudaFuncSetAttribute(k_gemm_h<1,1>, cudaFuncAttributeMaxDynamicSharedMemorySize, DSM);

    const int W2_OFF = KCP1 * 128;
    const int W3_OFF = KCP1 * 128 + 128 * 128;

    // Launch order arranged so gemm1 is launch index 5 (ncu -s 5 -c 1 captures it).
    k_newxyz<<<(Bb * Mq + 255) / 256, 256>>>(pxyz, ind, nxyz);              // 0
    k_transpose<<<dim3(Np / 32, Cf / 32, Bb), dim3(32, 8)>>>(feat, pFT);    // 1
    k_packW1<<<128, KCP1>>>(w1, pWh);                                       // 2
    k_packW23<<<384, 128>>>(w2, w3, pWh + W2_OFF, pWh + W3_OFF);            // 3
    k_ballquery<<<(Bb * Mq * 32) / 256, 256>>>(pxyz, nxyz);                 // 4

    // layer 1: fused gather/concat, K = 160 -> 5 chunks
    k_gemm_h<0,0><<<dim3(NCTA, 1), 256, DSM>>>(pWh, b1, 5, KCP1,            // 5 (profiled)
                                               nullptr, pxyz, nxyz, pY1);
    k_reduce<<<128, 256>>>(g1, be1);

    // layer 2: fused BN1+ReLU, K = 128 -> 4 chunks
    k_gemm_h<1,0><<<dim3(NCTA, 1), 256, DSM>>>(pWh + W2_OFF, b2, 4, 128,
                                               pY1, nullptr, nullptr, pY2);
    k_reduce<<<128, 256>>>(g2, be2);

    // layer 3: fused BN2+ReLU, 256 out channels, max fused into epilogue (no Y3)
    k_gemm_h<1,1><<<dim3(NCTA, 2), 256, DSM>>>(pWh + W3_OFF, b3, 4, 128,
                                               pY2, nullptr, nullptr, nullptr);
    k_reduce<<<256, 256>>>(g3, be3);

    // BN3+ReLU on per-query maxima (4MB read, 4MB write)
    k_final<<<(Bb * 256 * Mq) / 256, 256>>>(fout);
}

// round 10
// speedup vs baseline: 1.1208x; 1.1208x over previous
#include <cuda_runtime.h>
#include <cuda_fp16.h>
#include <cstdint>
#include <cstddef>

// ---------------- problem constants ----------------
#define Bb   4
#define Np   16384
#define Cf   128
#define Mq   1024
#define Kq   32
#define NNc  131072            // Bb*Mq*Kq (GEMM column count)
#define R2c  0.16f
#define EPSv 1e-5f
#define KCP1 160               // layer1 K storage pad (compute stops at 144)
#define NCTA 1024
#define NQ   4096              // total queries (B*M)

// ---------------- scratch (device globals) ----------------
__device__ int   g_idx[NNc];
__device__ __align__(16) __half g_Whf[KCP1*128 + 128*128 + 128*256];  // fp16 W, [o][cpad]
__device__ float g_featT[(size_t)Bb * Np * Cf];        // 32 MB
__device__ float g_Y1[(size_t)128 * NNc];              // 64 MB
__device__ float g_Y2[(size_t)128 * NNc];              // 64 MB
__device__ float g_mx[(size_t)256 * NQ];               // 4 MB  (layer3 raw max over K)
__device__ float g_ps[256 * NCTA];
__device__ float g_pq[256 * NCTA];
__device__ float g_scale[256];
__device__ float g_shift[256];

// ---------------- helpers ----------------
__device__ __forceinline__ uint32_t smem_u32(const void* p) {
    uint32_t a;
    asm("{ .reg .u64 t; cvta.to.shared.u64 t, %1; cvt.u32.u64 %0, t; }" : "=r"(a) : "l"(p));
    return a;
}
// pack two floats into f16x2 (lo, hi)
__device__ __forceinline__ uint32_t f22h(float lo, float hi) {
    uint32_t r;
    asm("cvt.rn.f16x2.f32 %0, %1, %2;" : "=r"(r) : "f"(hi), "f"(lo));
    return r;
}
#define CPASYNC16(dst, src) \
    asm volatile("cp.async.ca.shared.global [%0],[%1],16;" :: "r"(dst), "l"(src))
#define LDSM_X4(d0,d1,d2,d3,a) \
    asm volatile("ldmatrix.sync.aligned.m8n8.x4.shared.b16 {%0,%1,%2,%3},[%4];" \
                 : "=r"(d0),"=r"(d1),"=r"(d2),"=r"(d3) : "r"(a))
#define LDSM_X2(d0,d1,a) \
    asm volatile("ldmatrix.sync.aligned.m8n8.x2.shared.b16 {%0,%1},[%2];" \
                 : "=r"(d0),"=r"(d1) : "r"(a))
#define MMA16816(c, a, b) \
    asm volatile("mma.sync.aligned.m16n8k16.row.col.f32.f16.f16.f32 " \
                 "{%0,%1,%2,%3},{%4,%5,%6,%7},{%8,%9},{%0,%1,%2,%3};" \
                 : "+f"((c)[0]),"+f"((c)[1]),"+f"((c)[2]),"+f"((c)[3]) \
                 : "r"((a)[0]),"r"((a)[1]),"r"((a)[2]),"r"((a)[3]), \
                   "r"((b)[0]),"r"((b)[1]))

// ---------------- kernel: merged prep (newxyz gather + all weight packs) ----------------
// blocks 0..15:    newxyz (4096 items)
// blocks 16..143:  packW1 (o = blk-16), permuted channels, pad to KCP1
// blocks 144..271: packW2 (o = blk-144)
// blocks 272..527: packW3 (o = blk-272)
__global__ void k_prep(const float* __restrict__ pxyz, const int* __restrict__ ind,
                       const float* __restrict__ W1, const float* __restrict__ W2,
                       const float* __restrict__ W3,
                       float* __restrict__ nxyz, __half* __restrict__ Wh)
{
    const int W2_OFF = KCP1 * 128;
    const int W3_OFF = KCP1 * 128 + 128 * 128;
    int blk = blockIdx.x, t = threadIdx.x;
    if (blk < 16) {
        int i = blk * 256 + t;
        int b = i >> 10;
        int n = ind[i];
        const float* p = pxyz + ((size_t)b * Np + n) * 3;
        nxyz[i * 3 + 0] = p[0];
        nxyz[i * 3 + 1] = p[1];
        nxyz[i * 3 + 2] = p[2];
    } else if (blk < 144) {
        int o = blk - 16, c = t;
        if (c < KCP1) {
            float v = 0.f;
            int oc = (c < 128) ? (c + 3) : ((c < 131) ? (c - 128) : -1);
            if (oc >= 0) v = W1[o * 131 + oc];
            Wh[o * KCP1 + c] = __float2half_rn(v);
        }
    } else if (blk < 272) {
        int o = blk - 144;
        if (t < 128) Wh[W2_OFF + o * 128 + t] = __float2half_rn(W2[o * 128 + t]);
    } else {
        int o = blk - 272;
        if (t < 128) Wh[W3_OFF + o * 128 + t] = __float2half_rn(W3[o * 128 + t]);
    }
}

// ---------------- kernel: ball query (warp per query) ----------------
__global__ void k_ballquery(const float* __restrict__ pxyz, const float* __restrict__ nxyz)
{
    int gtid = blockIdx.x * blockDim.x + threadIdx.x;
    int q    = gtid >> 5;
    int lane = gtid & 31;
    int b    = q >> 10;

    float nx = nxyz[q * 3 + 0], ny = nxyz[q * 3 + 1], nz = nxyz[q * 3 + 2];
    const float* px = pxyz + (size_t)b * Np * 3;

    int cnt = 0, first = 0;
    for (int n0 = 0; n0 < Np; n0 += 32) {
        int n = n0 + lane;
        float dx = px[n * 3 + 0] - nx, dy = px[n * 3 + 1] - ny, dz = px[n * 3 + 2] - nz;
        float d2 = __fadd_rn(__fadd_rn(__fmul_rn(dx, dx), __fmul_rn(dy, dy)), __fmul_rn(dz, dz));
        bool within = d2 < R2c;
        unsigned bal = __ballot_sync(0xffffffffu, within);
        if (bal) {
            if (cnt == 0) first = n0 + __ffs(bal) - 1;
            int pre = __popc(bal & ((1u << lane) - 1u));
            if (within && (cnt + pre) < Kq) g_idx[q * Kq + cnt + pre] = n;
            cnt += __popc(bal);
            if (cnt >= Kq) break;
        }
    }
    cnt = min(cnt, Kq);
    if (lane >= cnt) g_idx[q * Kq + lane] = first;
}

// ---------------- kernel: transpose features -> featT[b][n][c] ----------------
__global__ void k_transpose(const float* __restrict__ f, float* __restrict__ ft)
{
    __shared__ float t[32][33];
    int b  = blockIdx.z;
    int n0 = blockIdx.x << 5, c0 = blockIdx.y << 5;
    int tx = threadIdx.x, ty = threadIdx.y;       // 32 x 8
#pragma unroll
    for (int i = 0; i < 32; i += 8)
        t[ty + i][tx] = f[((size_t)b * Cf + c0 + ty + i) * Np + n0 + tx];
    __syncthreads();
#pragma unroll
    for (int i = 0; i < 32; i += 8)
        ft[((size_t)b * Np + n0 + ty + i) * Cf + c0 + tx] = t[tx][ty + i];
}

// ---------------- fused fp16 GEMM (double-buffered, ldmatrix + m16n8k16) ----------------
// Y[o][n] = sum_c W[o][c] * X[n][c] + bias[o]; per-CTA channel partial stats.
// CTA tile 128(M) x 128(N), K-chunk 32; 8 warps 2(M)x4(N), warp tile 64x32.
// MODE 0: B generated by gather/concat on the fly (layer 1)
// MODE 1: B = relu(scale*Yprev + shift) (layers 2/3)
// DOMAX 1: no Y write; per-(row, query) max of accumulators -> g_mx.
// TAILKS: number of k16 steps in the LAST chunk (2 = full, 1 = half chunk).
#define SSTR 40                   // smem row stride in halves (80B, ldmatrix conflict-free)
#define ABUF (128 * SSTR)         // one A buffer in halves (5120)
template <int MODE, int DOMAX, int TAILKS>
__global__ void __launch_bounds__(256, 2) k_gemm_h(
    const __half* __restrict__ Wh, const float* __restrict__ bias,
    int kchunks, int KCpad,
    const float* __restrict__ Bsrc,
    const float* __restrict__ pxyz, const float* __restrict__ nxyz,
    float* __restrict__ Y)
{
    extern __shared__ __half dsm[];   // [A buf0][A buf1][B buf0][B buf1], each ABUF halves
    __shared__ float s_sum[128], s_sq[128];

    const int tid  = threadIdx.x;
    const int wid  = tid >> 5, lane = tid & 31;
    const int n0   = blockIdx.x << 7;
    const int o0   = blockIdx.y << 7;
    const int wm   = wid >> 2;
    const int wn   = wid & 3;

    if (tid < 128) { s_sum[tid] = 0.f; s_sq[tid] = 0.f; }

    float acc[4][4][4];
#pragma unroll
    for (int mt = 0; mt < 4; mt++)
#pragma unroll
        for (int nt = 0; nt < 4; nt++)
#pragma unroll
            for (int r = 0; r < 4; r++) acc[mt][nt][r] = 0.f;

    uint32_t pv[8];   // staged B halves (4 iters x 2 f16x2)

#define STAGE_A(KT, BUF) do {                                                  \
    uint32_t base = smem_u32(dsm) + (BUF) * (ABUF * 2);                        \
    _Pragma("unroll")                                                          \
    for (int s = 0; s < 2; s++) {                                              \
        int idx = tid + (s << 8);            /* 0..511 */                      \
        int row = idx >> 2, seg = idx & 3;                                     \
        const __half* src = Wh + (size_t)(o0 + row) * KCpad + (KT) * 32 + seg * 8; \
        CPASYNC16(base + row * (SSTR * 2) + seg * 16, src);                    \
    } } while (0)

#define PREFETCH_B(KT) do {                                                    \
    _Pragma("unroll")                                                          \
    for (int s = 0; s < 4; s++) {                                              \
        int idx = tid + (s << 8);                                              \
        int c4 = idx >> 7, j = idx & 127;    /* c4: 0..7, j: col in tile */    \
        int cg0 = (KT) * 32 + c4 * 4;                                          \
        float f0, f1, f2, f3;                                                  \
        if (MODE == 1) {                                                       \
            int n = n0 + j;                                                    \
            float y0 = Bsrc[(size_t)(cg0 + 0) * NNc + n];                      \
            float y1 = Bsrc[(size_t)(cg0 + 1) * NNc + n];                      \
            float y2 = Bsrc[(size_t)(cg0 + 2) * NNc + n];                      \
            float y3 = Bsrc[(size_t)(cg0 + 3) * NNc + n];                      \
            f0 = fmaxf(fmaf(g_scale[cg0 + 0], y0, g_shift[cg0 + 0]), 0.f);     \
            f1 = fmaxf(fmaf(g_scale[cg0 + 1], y1, g_shift[cg0 + 1]), 0.f);     \
            f2 = fmaxf(fmaf(g_scale[cg0 + 2], y2, g_shift[cg0 + 2]), 0.f);     \
            f3 = fmaxf(fmaf(g_scale[cg0 + 3], y3, g_shift[cg0 + 3]), 0.f);     \
        } else {                                                               \
            int col = n0 + j;                                                  \
            int idxv = g_idx[col];                                             \
            int b = col >> 15;                                                 \
            if (cg0 + 3 < 128) {                                               \
                float4 f = *(const float4*)&g_featT[((size_t)b*Np+idxv)*Cf+cg0]; \
                f0 = f.x; f1 = f.y; f2 = f.z; f3 = f.w;                        \
            } else {                                                           \
                int q = col >> 5;                                              \
                float fv[4];                                                   \
                _Pragma("unroll")                                              \
                for (int i2 = 0; i2 < 4; i2++) {                               \
                    int cg = cg0 + i2;                                         \
                    float x = 0.f;                                             \
                    if (cg < 128)                                              \
                        x = g_featT[((size_t)b * Np + idxv) * Cf + cg];        \
                    else if (cg < 131)                                         \
                        x = pxyz[((size_t)b * Np + idxv) * 3 + cg - 128]       \
                          - nxyz[q * 3 + cg - 128];                            \
                    fv[i2] = x;                                                \
                }                                                              \
                f0 = fv[0]; f1 = fv[1]; f2 = fv[2]; f3 = fv[3];                \
            }                                                                  \
        }                                                                      \
        pv[s * 2 + 0] = f22h(f0, f1);                                          \
        pv[s * 2 + 1] = f22h(f2, f3);                                          \
    } } while (0)

#define STAGE_B(BUF) do {                                                      \
    __half* sBc = dsm + 2 * ABUF + (BUF) * ABUF;                               \
    _Pragma("unroll")                                                          \
    for (int s = 0; s < 4; s++) {                                              \
        int idx = tid + (s << 8);                                              \
        int c4 = idx >> 7, j = idx & 127;                                      \
        *(uint2*)&sBc[j * SSTR + c4 * 4] = make_uint2(pv[s*2+0], pv[s*2+1]);   \
    } } while (0)

    // ---------- prologue ----------
    PREFETCH_B(0);
    STAGE_A(0, 0);
    STAGE_B(0);
    asm volatile("cp.async.wait_all;" ::: "memory");
    __syncthreads();

    // ldmatrix lane addressing (byte offsets into a buffer)
    const uint32_t rowA = ((wm * 64 + (lane & 15)) * SSTR + (lane >> 4) * 8) * 2;
    const uint32_t rowB = ((wn * 32 + (lane & 7)) * SSTR + ((lane >> 3) & 1) * 8) * 2;

    // ---------- pipelined mainloop ----------
    for (int kt = 0; kt < kchunks; kt++) {
        const int cur = kt & 1, nxt = cur ^ 1;
        const bool more = (kt + 1 < kchunks);
        if (more) {
            STAGE_A(kt + 1, nxt);      // async into alternate buffer
            PREFETCH_B(kt + 1);        // LDG into regs, overlaps MMA below
        }

        const uint32_t bA = smem_u32(dsm) + cur * (ABUF * 2);
        const uint32_t bB = smem_u32(dsm) + (2 + cur) * (ABUF * 2);
        const int nks = (kt == kchunks - 1) ? TAILKS : 2;
#pragma unroll
        for (int ks = 0; ks < 2; ks++) {
            if (ks >= nks) break;
            uint32_t ah[4][4], bh[4][2];
#pragma unroll
            for (int mt = 0; mt < 4; mt++) {
                uint32_t off = rowA + mt * (16 * SSTR * 2) + ks * 32;
                LDSM_X4(ah[mt][0], ah[mt][1], ah[mt][2], ah[mt][3], bA + off);
            }
#pragma unroll
            for (int nt = 0; nt < 4; nt++) {
                uint32_t off = rowB + nt * (8 * SSTR * 2) + ks * 32;
                LDSM_X2(bh[nt][0], bh[nt][1], bB + off);
            }
#pragma unroll
            for (int mt = 0; mt < 4; mt++)
#pragma unroll
                for (int nt = 0; nt < 4; nt++)
                    MMA16816(acc[mt][nt], ah[mt], bh[nt]);
        }

        if (more) STAGE_B(nxt);
        asm volatile("cp.async.wait_all;" ::: "memory");
        __syncthreads();
    }

    // ---------- epilogue ----------
    const int qid = lane >> 2;
    const int qt  = lane & 3;
#pragma unroll
    for (int mt = 0; mt < 4; mt++) {
        int m1 = wm * 64 + mt * 16 + qid;
        int m2 = m1 + 8;
        float bb1 = bias[o0 + m1], bb2 = bias[o0 + m2];
        float s1 = 0.f, q1 = 0.f, s2 = 0.f, q2 = 0.f;
        float mx1 = -3.4e38f, mx2 = -3.4e38f;
#pragma unroll
        for (int nt = 0; nt < 4; nt++) {
            float v0 = acc[mt][nt][0] + bb1, v1 = acc[mt][nt][1] + bb1;
            float v2 = acc[mt][nt][2] + bb2, v3 = acc[mt][nt][3] + bb2;
            if (!DOMAX) {
                int n = n0 + wn * 32 + nt * 8 + qt * 2;
                *(float2*)&Y[(size_t)(o0 + m1) * NNc + n] = make_float2(v0, v1);
                *(float2*)&Y[(size_t)(o0 + m2) * NNc + n] = make_float2(v2, v3);
            } else {
                mx1 = fmaxf(mx1, fmaxf(v0, v1));
                mx2 = fmaxf(mx2, fmaxf(v2, v3));
            }
            s1 += v0 + v1; q1 += v0 * v0 + v1 * v1;
            s2 += v2 + v3; q2 += v2 * v2 + v3 * v3;
        }
        s1 += __shfl_xor_sync(0xffffffffu, s1, 1); s1 += __shfl_xor_sync(0xffffffffu, s1, 2);
        q1 += __shfl_xor_sync(0xffffffffu, q1, 1); q1 += __shfl_xor_sync(0xffffffffu, q1, 2);
        s2 += __shfl_xor_sync(0xffffffffu, s2, 1); s2 += __shfl_xor_sync(0xffffffffu, s2, 2);
        q2 += __shfl_xor_sync(0xffffffffu, q2, 1); q2 += __shfl_xor_sync(0xffffffffu, q2, 2);
        if (DOMAX) {
            mx1 = fmaxf(mx1, __shfl_xor_sync(0xffffffffu, mx1, 1));
            mx1 = fmaxf(mx1, __shfl_xor_sync(0xffffffffu, mx1, 2));
            mx2 = fmaxf(mx2, __shfl_xor_sync(0xffffffffu, mx2, 1));
            mx2 = fmaxf(mx2, __shfl_xor_sync(0xffffffffu, mx2, 2));
            if (qt == 0) {
                int qidx = blockIdx.x * 4 + wn;     // warp tile N=32 == one query
                g_mx[(size_t)(o0 + m1) * NQ + qidx] = mx1;
                g_mx[(size_t)(o0 + m2) * NQ + qidx] = mx2;
            }
        }
        if (qt == 0) {
            atomicAdd(&s_sum[m1], s1); atomicAdd(&s_sq[m1], q1);
            atomicAdd(&s_sum[m2], s2); atomicAdd(&s_sq[m2], q2);
        }
    }
    __syncthreads();
    if (tid < 128) {
        g_ps[(size_t)(o0 + tid) * NCTA + blockIdx.x] = s_sum[tid];
        g_pq[(size_t)(o0 + tid) * NCTA + blockIdx.x] = s_sq[tid];
    }
#undef STAGE_A
#undef PREFETCH_B
#undef STAGE_B
}

// ---------------- kernel: reduce partials -> BN scale/shift ----------------
__global__ void k_reduce(const float* __restrict__ gam, const float* __restrict__ bet)
{
    __shared__ float ss[256], sq[256];
    int c = blockIdx.x, t = threadIdx.x;
    float s = g_ps[(size_t)c * NCTA + t]       + g_ps[(size_t)c * NCTA + 256 + t]
            + g_ps[(size_t)c * NCTA + 512 + t] + g_ps[(size_t)c * NCTA + 768 + t];
    float q = g_pq[(size_t)c * NCTA + t]       + g_pq[(size_t)c * NCTA + 256 + t]
            + g_pq[(size_t)c * NCTA + 512 + t] + g_pq[(size_t)c * NCTA + 768 + t];
    ss[t] = s; sq[t] = q;
    __syncthreads();
    for (int st = 128; st > 0; st >>= 1) {
        if (t < st) { ss[t] += ss[t + st]; sq[t] += sq[t + st]; }
        __syncthreads();
    }
    if (t == 0) {
        float mean = ss[0] * (1.f / NNc);
        float var  = sq[0] * (1.f / NNc) - mean * mean;
        float rs   = rsqrtf(var + EPSv);
        float sc   = gam[c] * rs;
        g_scale[c] = sc;
        g_shift[c] = fmaf(-mean, sc, bet[c]);
    }
}

// ---------------- kernel: BN3+ReLU applied to per-query max ----------------
__global__ void k_final(float* __restrict__ outf)
{
    int i = blockIdx.x * blockDim.x + threadIdx.x;   // 1048576
    int m = i & (Mq - 1);
    int o = (i >> 10) & 255;
    int b = i >> 18;
    float v = g_mx[(size_t)o * NQ + b * Mq + m];
    outf[((size_t)b * 256 + o) * Mq + m] = fmaxf(fmaf(g_scale[o], v, g_shift[o]), 0.f);
}

// ---------------- host launcher ----------------
extern "C" void kernel_launch(void* const* d_in, const int* in_sizes, int n_in,
                              void* d_out, int out_size)
{
    const float* pxyz = (const float*)d_in[0];
    const float* feat = (const float*)d_in[1];
    const int*   ind  = (const int*)d_in[2];
    const float* w1 = (const float*)d_in[3];  const float* b1 = (const float*)d_in[4];
    const float* g1 = (const float*)d_in[5];  const float* be1 = (const float*)d_in[6];
    const float* w2 = (const float*)d_in[7];  const float* b2 = (const float*)d_in[8];
    const float* g2 = (const float*)d_in[9];  const float* be2 = (const float*)d_in[10];
    const float* w3 = (const float*)d_in[11]; const float* b3 = (const float*)d_in[12];
    const float* g3 = (const float*)d_in[13]; const float* be3 = (const float*)d_in[14];

    float* out  = (float*)d_out;
    float* nxyz = out;
    float* fout = out + Bb * Mq * 3;

    float *pY1, *pY2, *pFT;
    __half* pWh;
    cudaGetSymbolAddress((void**)&pY1, g_Y1);
    cudaGetSymbolAddress((void**)&pY2, g_Y2);
    cudaGetSymbolAddress((void**)&pFT, g_featT);
    cudaGetSymbolAddress((void**)&pWh, g_Whf);

    const int DSM = 4 * ABUF * 2;   // 40960 bytes (A x2 + B x2, fp16)
    cudaFuncSetAttribute(k_gemm_h<0,0,1>, cudaFuncAttributeMaxDynamicSharedMemorySize, DSM);
    cudaFuncSetAttribute(k_gemm_h<1,0,2>, cudaFuncAttributeMaxDynamicSharedMemorySize, DSM);
    cudaFuncSetAttribute(k_gemm_h<1,1,2>, cudaFuncAttributeMaxDynamicSharedMemorySize, DSM);

    const int W2_OFF = KCP1 * 128;
    const int W3_OFF = KCP1 * 128 + 128 * 128;

    // launch 0: merged prep (newxyz + packW1/W2/W3)
    k_prep<<<528, 256>>>(pxyz, ind, w1, w2, w3, nxyz, pWh);
    // launch 1: ball query
    k_ballquery<<<(Bb * Mq * 32) / 256, 256>>>(pxyz, nxyz);
    // launch 2: feature transpose
    k_transpose<<<dim3(Np / 32, Cf / 32, Bb), dim3(32, 8)>>>(feat, pFT);

    // launch 3 (profiled slot): layer 1, K chunks 0-3 full + tail chunk (16 halves)
    k_gemm_h<0,0,1><<<dim3(NCTA, 1), 256, DSM>>>(pWh, b1, 5, KCP1,
                                                 nullptr, pxyz, nxyz, pY1);
    k_reduce<<<128, 256>>>(g1, be1);

    // layer 2: fused BN1+ReLU, K = 128 -> 4 chunks
    k_gemm_h<1,0,2><<<dim3(NCTA, 1), 256, DSM>>>(pWh + W2_OFF, b2, 4, 128,
                                                 pY1, nullptr, nullptr, pY2);
    k_reduce<<<128, 256>>>(g2, be2);

    // layer 3: fused BN2+ReLU, 256 out channels, max fused into epilogue (no Y3)
    k_gemm_h<1,1,2><<<dim3(NCTA, 2), 256, DSM>>>(pWh + W3_OFF, b3, 4, 128,
                                                 pY2, nullptr, nullptr, nullptr);
    k_reduce<<<256, 256>>>(g3, be3);

    // BN3+ReLU on per-query maxima (4MB read, 4MB write)
    k_final<<<(Bb * 256 * Mq) / 256, 256>>>(fout);
}

// round 11
// speedup vs baseline: 1.1227x; 1.0016x over previous
#include <cuda_runtime.h>
#include <cuda_fp16.h>
#include <cstdint>
#include <cstddef>

// ---------------- problem constants ----------------
#define Bb   4
#define Np   16384
#define Cf   128
#define Mq   1024
#define Kq   32
#define NNc  131072            // Bb*Mq*Kq (GEMM column count)
#define R2c  0.16f
#define EPSv 1e-5f
#define KCP1 160               // layer1 K storage pad (compute stops at 144)
#define NCTA 1024
#define NQ   4096              // total queries (B*M)

// ---------------- scratch (device globals) ----------------
__device__ int   g_idx[NNc];
__device__ __align__(16) __half g_Whf[KCP1*128 + 128*128 + 128*256];  // fp16 W, [o][cpad]
__device__ float g_featT[(size_t)Bb * Np * Cf];        // 32 MB
__device__ __align__(16) __half g_Y1h[(size_t)128 * NNc];   // 32 MB (fp16 activations)
__device__ __align__(16) __half g_Y2h[(size_t)128 * NNc];   // 32 MB
__device__ float g_mx[(size_t)256 * NQ];               // 4 MB  (layer3 raw max over K)
__device__ float g_ps[256 * NCTA];
__device__ float g_pq[256 * NCTA];
__device__ float g_scale[256];
__device__ float g_shift[256];

// ---------------- helpers ----------------
__device__ __forceinline__ uint32_t smem_u32(const void* p) {
    uint32_t a;
    asm("{ .reg .u64 t; cvta.to.shared.u64 t, %1; cvt.u32.u64 %0, t; }" : "=r"(a) : "l"(p));
    return a;
}
// pack two floats into f16x2 (lo, hi)
__device__ __forceinline__ uint32_t f22h(float lo, float hi) {
    uint32_t r;
    asm("cvt.rn.f16x2.f32 %0, %1, %2;" : "=r"(r) : "f"(hi), "f"(lo));
    return r;
}
#define CPASYNC16(dst, src) \
    asm volatile("cp.async.ca.shared.global [%0],[%1],16;" :: "r"(dst), "l"(src))
#define LDSM_X4(d0,d1,d2,d3,a) \
    asm volatile("ldmatrix.sync.aligned.m8n8.x4.shared.b16 {%0,%1,%2,%3},[%4];" \
                 : "=r"(d0),"=r"(d1),"=r"(d2),"=r"(d3) : "r"(a))
#define LDSM_X2(d0,d1,a) \
    asm volatile("ldmatrix.sync.aligned.m8n8.x2.shared.b16 {%0,%1},[%2];" \
                 : "=r"(d0),"=r"(d1) : "r"(a))
#define MMA16816(c, a, b) \
    asm volatile("mma.sync.aligned.m16n8k16.row.col.f32.f16.f16.f32 " \
                 "{%0,%1,%2,%3},{%4,%5,%6,%7},{%8,%9},{%0,%1,%2,%3};" \
                 : "+f"((c)[0]),"+f"((c)[1]),"+f"((c)[2]),"+f"((c)[3]) \
                 : "r"((a)[0]),"r"((a)[1]),"r"((a)[2]),"r"((a)[3]), \
                   "r"((b)[0]),"r"((b)[1]))

// ---------------- kernel: merged prep (newxyz gather + all weight packs) ----------------
__global__ void k_prep(const float* __restrict__ pxyz, const int* __restrict__ ind,
                       const float* __restrict__ W1, const float* __restrict__ W2,
                       const float* __restrict__ W3,
                       float* __restrict__ nxyz, __half* __restrict__ Wh)
{
    const int W2_OFF = KCP1 * 128;
    const int W3_OFF = KCP1 * 128 + 128 * 128;
    int blk = blockIdx.x, t = threadIdx.x;
    if (blk < 16) {
        int i = blk * 256 + t;
        int b = i >> 10;
        int n = ind[i];
        const float* p = pxyz + ((size_t)b * Np + n) * 3;
        nxyz[i * 3 + 0] = p[0];
        nxyz[i * 3 + 1] = p[1];
        nxyz[i * 3 + 2] = p[2];
    } else if (blk < 144) {
        int o = blk - 16, c = t;
        if (c < KCP1) {
            float v = 0.f;
            int oc = (c < 128) ? (c + 3) : ((c < 131) ? (c - 128) : -1);
            if (oc >= 0) v = W1[o * 131 + oc];
            Wh[o * KCP1 + c] = __float2half_rn(v);
        }
    } else if (blk < 272) {
        int o = blk - 144;
        if (t < 128) Wh[W2_OFF + o * 128 + t] = __float2half_rn(W2[o * 128 + t]);
    } else {
        int o = blk - 272;
        if (t < 128) Wh[W3_OFF + o * 128 + t] = __float2half_rn(W3[o * 128 + t]);
    }
}

// ---------------- kernel: ball query (warp per query) ----------------
__global__ void k_ballquery(const float* __restrict__ pxyz, const float* __restrict__ nxyz)
{
    int gtid = blockIdx.x * blockDim.x + threadIdx.x;
    int q    = gtid >> 5;
    int lane = gtid & 31;
    int b    = q >> 10;

    float nx = nxyz[q * 3 + 0], ny = nxyz[q * 3 + 1], nz = nxyz[q * 3 + 2];
    const float* px = pxyz + (size_t)b * Np * 3;

    int cnt = 0, first = 0;
    for (int n0 = 0; n0 < Np; n0 += 32) {
        int n = n0 + lane;
        float dx = px[n * 3 + 0] - nx, dy = px[n * 3 + 1] - ny, dz = px[n * 3 + 2] - nz;
        float d2 = __fadd_rn(__fadd_rn(__fmul_rn(dx, dx), __fmul_rn(dy, dy)), __fmul_rn(dz, dz));
        bool within = d2 < R2c;
        unsigned bal = __ballot_sync(0xffffffffu, within);
        if (bal) {
            if (cnt == 0) first = n0 + __ffs(bal) - 1;
            int pre = __popc(bal & ((1u << lane) - 1u));
            if (within && (cnt + pre) < Kq) g_idx[q * Kq + cnt + pre] = n;
            cnt += __popc(bal);
            if (cnt >= Kq) break;
        }
    }
    cnt = min(cnt, Kq);
    if (lane >= cnt) g_idx[q * Kq + lane] = first;
}

// ---------------- kernel: transpose features -> featT[b][n][c] ----------------
__global__ void k_transpose(const float* __restrict__ f, float* __restrict__ ft)
{
    __shared__ float t[32][33];
    int b  = blockIdx.z;
    int n0 = blockIdx.x << 5, c0 = blockIdx.y << 5;
    int tx = threadIdx.x, ty = threadIdx.y;       // 32 x 8
#pragma unroll
    for (int i = 0; i < 32; i += 8)
        t[ty + i][tx] = f[((size_t)b * Cf + c0 + ty + i) * Np + n0 + tx];
    __syncthreads();
#pragma unroll
    for (int i = 0; i < 32; i += 8)
        ft[((size_t)b * Np + n0 + ty + i) * Cf + c0 + tx] = t[tx][ty + i];
}

// ---------------- fused fp16 GEMM (double-buffered, ldmatrix + m16n8k16) ----------------
// CTA tile 128(M) x 128(N), K-chunk 32; 8 warps 2(M)x4(N), warp tile 64x32.
// MODE 0: B gathered/concat on the fly (layer 1), warp-coalesced row loads.
// MODE 1: B = relu(scale*Yprev + shift), Yprev fp16.
// DOMAX 1: no Y write; per-(row, query) max of accumulators -> g_mx.
// TAILKS: k16 steps in last chunk (2 = full, 1 = half).
#define SSTR 40                   // smem row stride in halves (80B)
#define ABUF (128 * SSTR)         // one A buffer in halves (5120)
template <int MODE, int DOMAX, int TAILKS>
__global__ void __launch_bounds__(256, 2) k_gemm_h(
    const __half* __restrict__ Wh, const float* __restrict__ bias,
    int kchunks, int KCpad,
    const __half* __restrict__ Bsrc,
    const float* __restrict__ pxyz, const float* __restrict__ nxyz,
    __half* __restrict__ Y)
{
    extern __shared__ __half dsm[];   // [A buf0][A buf1][B buf0][B buf1], each ABUF halves
    __shared__ float s_sum[128], s_sq[128];

    const int tid  = threadIdx.x;
    const int wid  = tid >> 5, lane = tid & 31;
    const int n0   = blockIdx.x << 7;
    const int o0   = blockIdx.y << 7;
    const int wm   = wid >> 2;
    const int wn   = wid & 3;

    if (tid < 128) { s_sum[tid] = 0.f; s_sq[tid] = 0.f; }

    float acc[4][4][4];
#pragma unroll
    for (int mt = 0; mt < 4; mt++)
#pragma unroll
        for (int nt = 0; nt < 4; nt++)
#pragma unroll
            for (int r = 0; r < 4; r++) acc[mt][nt][r] = 0.f;

    uint32_t pv[8];   // staged B halves (4 iters x 2 f16x2)

#define STAGE_A(KT, BUF) do {                                                  \
    uint32_t base = smem_u32(dsm) + (BUF) * (ABUF * 2);                        \
    _Pragma("unroll")                                                          \
    for (int s = 0; s < 2; s++) {                                              \
        int idx = tid + (s << 8);            /* 0..511 */                      \
        int row = idx >> 2, seg = idx & 3;                                     \
        const __half* src = Wh + (size_t)(o0 + row) * KCpad + (KT) * 32 + seg * 8; \
        CPASYNC16(base + row * (SSTR * 2) + seg * 16, src);                    \
    } } while (0)

// MODE 0: 8 consecutive lanes cover ONE column's 32-channel chunk (128B, coalesced).
// MODE 1: lane-per-column, channel-major (coalesced 16-bit loads).
#define PREFETCH_B(KT) do {                                                    \
    _Pragma("unroll")                                                          \
    for (int s = 0; s < 4; s++) {                                              \
        int idx = tid + (s << 8);                                              \
        float f0, f1, f2, f3;                                                  \
        if (MODE == 1) {                                                       \
            int c4 = idx >> 7, j = idx & 127;                                  \
            int cg0 = (KT) * 32 + c4 * 4;                                      \
            int n = n0 + j;                                                    \
            float y0 = __half2float(Bsrc[(size_t)(cg0 + 0) * NNc + n]);        \
            float y1 = __half2float(Bsrc[(size_t)(cg0 + 1) * NNc + n]);        \
            float y2 = __half2float(Bsrc[(size_t)(cg0 + 2) * NNc + n]);        \
            float y3 = __half2float(Bsrc[(size_t)(cg0 + 3) * NNc + n]);        \
            f0 = fmaxf(fmaf(g_scale[cg0 + 0], y0, g_shift[cg0 + 0]), 0.f);     \
            f1 = fmaxf(fmaf(g_scale[cg0 + 1], y1, g_shift[cg0 + 1]), 0.f);     \
            f2 = fmaxf(fmaf(g_scale[cg0 + 2], y2, g_shift[cg0 + 2]), 0.f);     \
            f3 = fmaxf(fmaf(g_scale[cg0 + 3], y3, g_shift[cg0 + 3]), 0.f);     \
        } else {                                                               \
            int colL = idx >> 3, l8 = idx & 7;                                 \
            int cg0 = (KT) * 32 + l8 * 4;                                      \
            int col = n0 + colL;                                               \
            int idxv = g_idx[col];                                             \
            int b = col >> 15;                                                 \
            if (cg0 + 3 < 128) {                                               \
                float4 f = *(const float4*)&g_featT[((size_t)b*Np+idxv)*Cf+cg0]; \
                f0 = f.x; f1 = f.y; f2 = f.z; f3 = f.w;                        \
            } else {                                                           \
                int q = col >> 5;                                              \
                float fv[4];                                                   \
                _Pragma("unroll")                                              \
                for (int i2 = 0; i2 < 4; i2++) {                               \
                    int cg = cg0 + i2;                                         \
                    float x = 0.f;                                             \
                    if (cg < 128)                                              \
                        x = g_featT[((size_t)b * Np + idxv) * Cf + cg];        \
                    else if (cg < 131)                                         \
                        x = pxyz[((size_t)b * Np + idxv) * 3 + cg - 128]       \
                          - nxyz[q * 3 + cg - 128];                            \
                    fv[i2] = x;                                                \
                }                                                              \
                f0 = fv[0]; f1 = fv[1]; f2 = fv[2]; f3 = fv[3];                \
            }                                                                  \
        }                                                                      \
        pv[s * 2 + 0] = f22h(f0, f1);                                          \
        pv[s * 2 + 1] = f22h(f2, f3);                                          \
    } } while (0)

#define STAGE_B(BUF) do {                                                      \
    __half* sBc = dsm + 2 * ABUF + (BUF) * ABUF;                               \
    _Pragma("unroll")                                                          \
    for (int s = 0; s < 4; s++) {                                              \
        int idx = tid + (s << 8);                                              \
        int jrow, coff;                                                        \
        if (MODE == 1) { jrow = idx & 127; coff = (idx >> 7) * 4; }            \
        else           { jrow = idx >> 3;  coff = (idx & 7) * 4;  }            \
        *(uint2*)&sBc[jrow * SSTR + coff] = make_uint2(pv[s*2+0], pv[s*2+1]);  \
    } } while (0)

    // ---------- prologue ----------
    PREFETCH_B(0);
    STAGE_A(0, 0);
    STAGE_B(0);
    asm volatile("cp.async.wait_all;" ::: "memory");
    __syncthreads();

    // ldmatrix lane addressing (byte offsets into a buffer)
    const uint32_t rowA = ((wm * 64 + (lane & 15)) * SSTR + (lane >> 4) * 8) * 2;
    const uint32_t rowB = ((wn * 32 + (lane & 7)) * SSTR + ((lane >> 3) & 1) * 8) * 2;

    // ---------- pipelined mainloop ----------
    for (int kt = 0; kt < kchunks; kt++) {
        const int cur = kt & 1, nxt = cur ^ 1;
        const bool more = (kt + 1 < kchunks);
        if (more) {
            STAGE_A(kt + 1, nxt);      // async into alternate buffer
            PREFETCH_B(kt + 1);        // LDG into regs, overlaps MMA below
        }

        const uint32_t bA = smem_u32(dsm) + cur * (ABUF * 2);
        const uint32_t bB = smem_u32(dsm) + (2 + cur) * (ABUF * 2);
        const int nks = (kt == kchunks - 1) ? TAILKS : 2;
#pragma unroll
        for (int ks = 0; ks < 2; ks++) {
            if (ks >= nks) break;
            uint32_t ah[4][4], bh[4][2];
#pragma unroll
            for (int mt = 0; mt < 4; mt++) {
                uint32_t off = rowA + mt * (16 * SSTR * 2) + ks * 32;
                LDSM_X4(ah[mt][0], ah[mt][1], ah[mt][2], ah[mt][3], bA + off);
            }
#pragma unroll
            for (int nt = 0; nt < 4; nt++) {
                uint32_t off = rowB + nt * (8 * SSTR * 2) + ks * 32;
                LDSM_X2(bh[nt][0], bh[nt][1], bB + off);
            }
#pragma unroll
            for (int mt = 0; mt < 4; mt++)
#pragma unroll
                for (int nt = 0; nt < 4; nt++)
                    MMA16816(acc[mt][nt], ah[mt], bh[nt]);
        }

        if (more) STAGE_B(nxt);
        asm volatile("cp.async.wait_all;" ::: "memory");
        __syncthreads();
    }

    // ---------- epilogue ----------
    const int qid = lane >> 2;
    const int qt  = lane & 3;
#pragma unroll
    for (int mt = 0; mt < 4; mt++) {
        int m1 = wm * 64 + mt * 16 + qid;
        int m2 = m1 + 8;
        float bb1 = bias[o0 + m1], bb2 = bias[o0 + m2];
        float s1 = 0.f, q1 = 0.f, s2 = 0.f, q2 = 0.f;
        float mx1 = -3.4e38f, mx2 = -3.4e38f;
#pragma unroll
        for (int nt = 0; nt < 4; nt++) {
            float v0 = acc[mt][nt][0] + bb1, v1 = acc[mt][nt][1] + bb1;
            float v2 = acc[mt][nt][2] + bb2, v3 = acc[mt][nt][3] + bb2;
            if (!DOMAX) {
                int n = n0 + wn * 32 + nt * 8 + qt * 2;
                *(uint32_t*)&Y[(size_t)(o0 + m1) * NNc + n] = f22h(v0, v1);
                *(uint32_t*)&Y[(size_t)(o0 + m2) * NNc + n] = f22h(v2, v3);
            } else {
                mx1 = fmaxf(mx1, fmaxf(v0, v1));
                mx2 = fmaxf(mx2, fmaxf(v2, v3));
            }
            s1 += v0 + v1; q1 += v0 * v0 + v1 * v1;
            s2 += v2 + v3; q2 += v2 * v2 + v3 * v3;
        }
        s1 += __shfl_xor_sync(0xffffffffu, s1, 1); s1 += __shfl_xor_sync(0xffffffffu, s1, 2);
        q1 += __shfl_xor_sync(0xffffffffu, q1, 1); q1 += __shfl_xor_sync(0xffffffffu, q1, 2);
        s2 += __shfl_xor_sync(0xffffffffu, s2, 1); s2 += __shfl_xor_sync(0xffffffffu, s2, 2);
        q2 += __shfl_xor_sync(0xffffffffu, q2, 1); q2 += __shfl_xor_sync(0xffffffffu, q2, 2);
        if (DOMAX) {
            mx1 = fmaxf(mx1, __shfl_xor_sync(0xffffffffu, mx1, 1));
            mx1 = fmaxf(mx1, __shfl_xor_sync(0xffffffffu, mx1, 2));
            mx2 = fmaxf(mx2, __shfl_xor_sync(0xffffffffu, mx2, 1));
            mx2 = fmaxf(mx2, __shfl_xor_sync(0xffffffffu, mx2, 2));
            if (qt == 0) {
                int qidx = blockIdx.x * 4 + wn;     // warp tile N=32 == one query
                g_mx[(size_t)(o0 + m1) * NQ + qidx] = mx1;
                g_mx[(size_t)(o0 + m2) * NQ + qidx] = mx2;
            }
        }
        if (qt == 0) {
            atomicAdd(&s_sum[m1], s1); atomicAdd(&s_sq[m1], q1);
            atomicAdd(&s_sum[m2], s2); atomicAdd(&s_sq[m2], q2);
        }
    }
    __syncthreads();
    if (tid < 128) {
        g_ps[(size_t)(o0 + tid) * NCTA + blockIdx.x] = s_sum[tid];
        g_pq[(size_t)(o0 + tid) * NCTA + blockIdx.x] = s_sq[tid];
    }
#undef STAGE_A
#undef PREFETCH_B
#undef STAGE_B
}

// ---------------- kernel: reduce partials -> BN scale/shift ----------------
__global__ void k_reduce(const float* __restrict__ gam, const float* __restrict__ bet)
{
    __shared__ float ss[256], sq[256];
    int c = blockIdx.x, t = threadIdx.x;
    float s = g_ps[(size_t)c * NCTA + t]       + g_ps[(size_t)c * NCTA + 256 + t]
            + g_ps[(size_t)c * NCTA + 512 + t] + g_ps[(size_t)c * NCTA + 768 + t];
    float q = g_pq[(size_t)c * NCTA + t]       + g_pq[(size_t)c * NCTA + 256 + t]
            + g_pq[(size_t)c * NCTA + 512 + t] + g_pq[(size_t)c * NCTA + 768 + t];
    ss[t] = s; sq[t] = q;
    __syncthreads();
    for (int st = 128; st > 0; st >>= 1) {
        if (t < st) { ss[t] += ss[t + st]; sq[t] += sq[t + st]; }
        __syncthreads();
    }
    if (t == 0) {
        float mean = ss[0] * (1.f / NNc);
        float var  = sq[0] * (1.f / NNc) - mean * mean;
        float rs   = rsqrtf(var + EPSv);
        float sc   = gam[c] * rs;
        g_scale[c] = sc;
        g_shift[c] = fmaf(-mean, sc, bet[c]);
    }
}

// ---------------- kernel: BN3+ReLU applied to per-query max ----------------
__global__ void k_final(float* __restrict__ outf)
{
    int i = blockIdx.x * blockDim.x + threadIdx.x;   // 1048576
    int m = i & (Mq - 1);
    int o = (i >> 10) & 255;
    int b = i >> 18;
    float v = g_mx[(size_t)o * NQ + b * Mq + m];
    outf[((size_t)b * 256 + o) * Mq + m] = fmaxf(fmaf(g_scale[o], v, g_shift[o]), 0.f);
}

// ---------------- host launcher ----------------
extern "C" void kernel_launch(void* const* d_in, const int* in_sizes, int n_in,
                              void* d_out, int out_size)
{
    const float* pxyz = (const float*)d_in[0];
    const float* feat = (const float*)d_in[1];
    const int*   ind  = (const int*)d_in[2];
    const float* w1 = (const float*)d_in[3];  const float* b1 = (const float*)d_in[4];
    const float* g1 = (const float*)d_in[5];  const float* be1 = (const float*)d_in[6];
    const float* w2 = (const float*)d_in[7];  const float* b2 = (const float*)d_in[8];
    const float* g2 = (const float*)d_in[9];  const float* be2 = (const float*)d_in[10];
    const float* w3 = (const float*)d_in[11]; const float* b3 = (const float*)d_in[12];
    const float* g3 = (const float*)d_in[13]; const float* be3 = (const float*)d_in[14];

    float* out  = (float*)d_out;
    float* nxyz = out;
    float* fout = out + Bb * Mq * 3;

    float *pFT;
    __half *pWh, *pY1h, *pY2h;
    cudaGetSymbolAddress((void**)&pFT, g_featT);
    cudaGetSymbolAddress((void**)&pWh, g_Whf);
    cudaGetSymbolAddress((void**)&pY1h, g_Y1h);
    cudaGetSymbolAddress((void**)&pY2h, g_Y2h);

    const int DSM = 4 * ABUF * 2;   // 40960 bytes (A x2 + B x2, fp16)
    cudaFuncSetAttribute(k_gemm_h<0,0,1>, cudaFuncAttributeMaxDynamicSharedMemorySize, DSM);
    cudaFuncSetAttribute(k_gemm_h<1,0,2>, cudaFuncAttributeMaxDynamicSharedMemorySize, DSM);
    cudaFuncSetAttribute(k_gemm_h<1,1,2>, cudaFuncAttributeMaxDynamicSharedMemorySize, DSM);

    const int W2_OFF = KCP1 * 128;
    const int W3_OFF = KCP1 * 128 + 128 * 128;

    // launch 0: merged prep (newxyz + packW1/W2/W3)
    k_prep<<<528, 256>>>(pxyz, ind, w1, w2, w3, nxyz, pWh);
    // launch 1: ball query
    k_ballquery<<<(Bb * Mq * 32) / 256, 256>>>(pxyz, nxyz);
    // launch 2: feature transpose
    k_transpose<<<dim3(Np / 32, Cf / 32, Bb), dim3(32, 8)>>>(feat, pFT);

    // launch 3 (profiled slot): layer 1, 4 full chunks + 16-channel tail
    k_gemm_h<0,0,1><<<dim3(NCTA, 1), 256, DSM>>>(pWh, b1, 5, KCP1,
                                                 nullptr, pxyz, nxyz, pY1h);
    k_reduce<<<128, 256>>>(g1, be1);

    // layer 2: fused BN1+ReLU, K = 128 -> 4 chunks
    k_gemm_h<1,0,2><<<dim3(NCTA, 1), 256, DSM>>>(pWh + W2_OFF, b2, 4, 128,
                                                 pY1h, nullptr, nullptr, pY2h);
    k_reduce<<<128, 256>>>(g2, be2);

    // layer 3: fused BN2+ReLU, 256 out channels, max fused into epilogue (no Y3)
    k_gemm_h<1,1,2><<<dim3(NCTA, 2), 256, DSM>>>(pWh + W3_OFF, b3, 4, 128,
                                                 pY2h, nullptr, nullptr, nullptr);
    k_reduce<<<256, 256>>>(g3, be3);

    // BN3+ReLU on per-query maxima (4MB read, 4MB write)
    k_final<<<(Bb * 256 * Mq) / 256, 256>>>(fout);
}

// round 12
// speedup vs baseline: 1.2826x; 1.1425x over previous
#include <cuda_runtime.h>
#include <cuda_fp16.h>
#include <cstdint>
#include <cstddef>

// ---------------- problem constants ----------------
#define Bb   4
#define Np   16384
#define Cf   128
#define Mq   1024
#define Kq   32
#define NNc  131072            // Bb*Mq*Kq (GEMM column count)
#define R2c  0.16f
#define EPSv 1e-5f
#define KCP1 160               // layer1 W storage stride (compute uses 144)
#define NCTA 1024
#define NQ   4096              // total queries (B*M)

// ---------------- scratch (device globals) ----------------
__device__ int   g_idx[NNc];
__device__ __align__(16) __half g_Whf[KCP1*128 + 128*128 + 128*256];  // fp16 W, [o][cpad]
__device__ float g_featT[(size_t)Bb * Np * Cf];        // 32 MB
__device__ __align__(16) __half g_Y1h[(size_t)128 * NNc];   // 32 MB (fp16 activations)
__device__ __align__(16) __half g_Y2h[(size_t)128 * NNc];   // 32 MB
__device__ float g_mx[(size_t)256 * NQ];               // 4 MB  (layer3 raw max over K)
__device__ float g_ps[256 * NCTA];
__device__ float g_pq[256 * NCTA];
__device__ float g_scale[256];
__device__ float g_shift[256];

// ---------------- helpers ----------------
__device__ __forceinline__ uint32_t smem_u32(const void* p) {
    uint32_t a;
    asm("{ .reg .u64 t; cvta.to.shared.u64 t, %1; cvt.u32.u64 %0, t; }" : "=r"(a) : "l"(p));
    return a;
}
// pack two floats into f16x2 (lo, hi)
__device__ __forceinline__ uint32_t f22h(float lo, float hi) {
    uint32_t r;
    asm("cvt.rn.f16x2.f32 %0, %1, %2;" : "=r"(r) : "f"(hi), "f"(lo));
    return r;
}
#define CPASYNC16(dst, src) \
    asm volatile("cp.async.ca.shared.global [%0],[%1],16;" :: "r"(dst), "l"(src))
#define LDSM_X4(d0,d1,d2,d3,a) \
    asm volatile("ldmatrix.sync.aligned.m8n8.x4.shared.b16 {%0,%1,%2,%3},[%4];" \
                 : "=r"(d0),"=r"(d1),"=r"(d2),"=r"(d3) : "r"(a))
#define LDSM_X2(d0,d1,a) \
    asm volatile("ldmatrix.sync.aligned.m8n8.x2.shared.b16 {%0,%1},[%2];" \
                 : "=r"(d0),"=r"(d1) : "r"(a))
#define MMA16816(c, a, b) \
    asm volatile("mma.sync.aligned.m16n8k16.row.col.f32.f16.f16.f32 " \
                 "{%0,%1,%2,%3},{%4,%5,%6,%7},{%8,%9},{%0,%1,%2,%3};" \
                 : "+f"((c)[0]),"+f"((c)[1]),"+f"((c)[2]),"+f"((c)[3]) \
                 : "r"((a)[0]),"r"((a)[1]),"r"((a)[2]),"r"((a)[3]), \
                   "r"((b)[0]),"r"((b)[1]))

// ---------------- kernel: merged prep (newxyz gather + all weight packs) ----------------
__global__ void k_prep(const float* __restrict__ pxyz, const int* __restrict__ ind,
                       const float* __restrict__ W1, const float* __restrict__ W2,
                       const float* __restrict__ W3,
                       float* __restrict__ nxyz, __half* __restrict__ Wh)
{
    const int W2_OFF = KCP1 * 128;
    const int W3_OFF = KCP1 * 128 + 128 * 128;
    int blk = blockIdx.x, t = threadIdx.x;
    if (blk < 16) {
        int i = blk * 256 + t;
        int b = i >> 10;
        int n = ind[i];
        const float* p = pxyz + ((size_t)b * Np + n) * 3;
        nxyz[i * 3 + 0] = p[0];
        nxyz[i * 3 + 1] = p[1];
        nxyz[i * 3 + 2] = p[2];
    } else if (blk < 144) {
        int o = blk - 16, c = t;
        if (c < KCP1) {
            float v = 0.f;
            int oc = (c < 128) ? (c + 3) : ((c < 131) ? (c - 128) : -1);
            if (oc >= 0) v = W1[o * 131 + oc];
            Wh[o * KCP1 + c] = __float2half_rn(v);
        }
    } else if (blk < 272) {
        int o = blk - 144;
        if (t < 128) Wh[W2_OFF + o * 128 + t] = __float2half_rn(W2[o * 128 + t]);
    } else {
        int o = blk - 272;
        if (t < 128) Wh[W3_OFF + o * 128 + t] = __float2half_rn(W3[o * 128 + t]);
    }
}

// ---------------- kernel: ball query (warp per query) ----------------
__global__ void k_ballquery(const float* __restrict__ pxyz, const float* __restrict__ nxyz)
{
    int gtid = blockIdx.x * blockDim.x + threadIdx.x;
    int q    = gtid >> 5;
    int lane = gtid & 31;
    int b    = q >> 10;

    float nx = nxyz[q * 3 + 0], ny = nxyz[q * 3 + 1], nz = nxyz[q * 3 + 2];
    const float* px = pxyz + (size_t)b * Np * 3;

    int cnt = 0, first = 0;
    for (int n0 = 0; n0 < Np; n0 += 32) {
        int n = n0 + lane;
        float dx = px[n * 3 + 0] - nx, dy = px[n * 3 + 1] - ny, dz = px[n * 3 + 2] - nz;
        float d2 = __fadd_rn(__fadd_rn(__fmul_rn(dx, dx), __fmul_rn(dy, dy)), __fmul_rn(dz, dz));
        bool within = d2 < R2c;
        unsigned bal = __ballot_sync(0xffffffffu, within);
        if (bal) {
            if (cnt == 0) first = n0 + __ffs(bal) - 1;
            int pre = __popc(bal & ((1u << lane) - 1u));
            if (within && (cnt + pre) < Kq) g_idx[q * Kq + cnt + pre] = n;
            cnt += __popc(bal);
            if (cnt >= Kq) break;
        }
    }
    cnt = min(cnt, Kq);
    if (lane >= cnt) g_idx[q * Kq + lane] = first;
}

// ---------------- kernel: transpose features -> featT[b][n][c] ----------------
__global__ void k_transpose(const float* __restrict__ f, float* __restrict__ ft)
{
    __shared__ float t[32][33];
    int b  = blockIdx.z;
    int n0 = blockIdx.x << 5, c0 = blockIdx.y << 5;
    int tx = threadIdx.x, ty = threadIdx.y;       // 32 x 8
#pragma unroll
    for (int i = 0; i < 32; i += 8)
        t[ty + i][tx] = f[((size_t)b * Cf + c0 + ty + i) * Np + n0 + tx];
    __syncthreads();
#pragma unroll
    for (int i = 0; i < 32; i += 8)
        ft[((size_t)b * Np + n0 + ty + i) * Cf + c0 + tx] = t[tx][ty + i];
}

// ---------------- one-shot fused fp16 GEMM (entire K staged once) ----------------
// CTA tile 128(M) x 128(N), FULL K in smem; 8 warps 2(M)x4(N), warp tile 64x32.
// KH: K halves staged/computed (144 layer1, 128 layers 2/3). One sync, no mainloop.
// MODE 0: B gathered/concat on the fly (layer 1).
// MODE 1: B = relu(scale*Yprev + shift), Yprev fp16.
// DOMAX 1: no Y write; per-(row, query) max of accumulators -> g_mx.
template <int KH, int MODE, int DOMAX>
__global__ void __launch_bounds__(256, 2) k_gemm_h(
    const __half* __restrict__ Wh, const float* __restrict__ bias,
    int KCpad,
    const __half* __restrict__ Bsrc,
    const float* __restrict__ pxyz, const float* __restrict__ nxyz,
    __half* __restrict__ Y)
{
    constexpr int SSTR = KH + 8;         // row stride in halves (conflict-free)
    constexpr int KHD8 = KH / 8;         // 16B chunks per A row
    constexpr int KS   = KH / 16;        // k16 steps
    extern __shared__ __half dsm[];      // [A: 128*SSTR][B: 128*SSTR]
    __half* sA = dsm;
    __half* sB = dsm + 128 * SSTR;
    __shared__ float s_sum[128], s_sq[128];

    const int tid  = threadIdx.x;
    const int wid  = tid >> 5, lane = tid & 31;
    const int n0   = blockIdx.x << 7;
    const int o0   = blockIdx.y << 7;
    const int wm   = wid >> 2;
    const int wn   = wid & 3;

    if (tid < 128) { s_sum[tid] = 0.f; s_sq[tid] = 0.f; }

    // ---------- stage A: full 128 x KH tile via cp.async ----------
    {
        uint32_t base = smem_u32(sA);
#pragma unroll
        for (int s = 0; s < (128 * KHD8) / 256; s++) {
            int i   = tid + s * 256;
            int row = i / KHD8;
            int seg = i - row * KHD8;
            const __half* src = Wh + (size_t)(o0 + row) * KCpad + seg * 8;
            CPASYNC16(base + (row * SSTR + seg * 8) * 2, src);
        }
    }

    // ---------- stage B: full 128 x KH tile ----------
    if (MODE == 0) {
        // feat channels 0..127: 32 lanes cover one column's 128 floats (coalesced)
#pragma unroll
        for (int s = 0; s < 16; s++) {
            int i    = tid + (s << 8);
            int colL = i >> 5;
            int ch4  = (i & 31) << 2;
            int col  = n0 + colL;
            int idxv = g_idx[col];
            int b    = col >> 15;
            float4 f = *(const float4*)&g_featT[((size_t)b * Np + idxv) * Cf + ch4];
            *(uint2*)&sB[colL * SSTR + ch4] =
                make_uint2(f22h(f.x, f.y), f22h(f.z, f.w));
        }
        // tail channels 128..143: xyz diffs + zero pad (threads 0..127, one col each)
        if (tid < 128) {
            int col  = n0 + tid;
            int idxv = g_idx[col];
            int b    = col >> 15;
            int q    = col >> 5;
            const float* p  = &pxyz[((size_t)b * Np + idxv) * 3];
            float d0 = p[0] - nxyz[q * 3 + 0];
            float d1 = p[1] - nxyz[q * 3 + 1];
            float d2 = p[2] - nxyz[q * 3 + 2];
            uint4 u0; u0.x = f22h(d0, d1); u0.y = f22h(d2, 0.f); u0.z = 0u; u0.w = 0u;
            uint4 z = make_uint4(0u, 0u, 0u, 0u);
            *(uint4*)&sB[tid * SSTR + 128] = u0;
            *(uint4*)&sB[tid * SSTR + 136] = z;
        }
    } else {
        // BN+ReLU from fp16 Y planes; adjacent threads -> adjacent columns (coalesced)
#pragma unroll
        for (int s = 0; s < 16; s++) {
            int i   = tid + (s << 8);
            int col = i & 127;
            int cg0 = (i >> 7) << 2;
            int n   = n0 + col;
            float y0 = __half2float(Bsrc[(size_t)(cg0 + 0) * NNc + n]);
            float y1 = __half2float(Bsrc[(size_t)(cg0 + 1) * NNc + n]);
            float y2 = __half2float(Bsrc[(size_t)(cg0 + 2) * NNc + n]);
            float y3 = __half2float(Bsrc[(size_t)(cg0 + 3) * NNc + n]);
            float f0 = fmaxf(fmaf(g_scale[cg0 + 0], y0, g_shift[cg0 + 0]), 0.f);
            float f1 = fmaxf(fmaf(g_scale[cg0 + 1], y1, g_shift[cg0 + 1]), 0.f);
            float f2 = fmaxf(fmaf(g_scale[cg0 + 2], y2, g_shift[cg0 + 2]), 0.f);
            float f3 = fmaxf(fmaf(g_scale[cg0 + 3], y3, g_shift[cg0 + 3]), 0.f);
            *(uint2*)&sB[col * SSTR + cg0] = make_uint2(f22h(f0, f1), f22h(f2, f3));
        }
    }

    asm volatile("cp.async.wait_all;" ::: "memory");
    __syncthreads();

    // ---------- compute: unbroken KS-step MMA stream ----------
    float acc[4][4][4];
#pragma unroll
    for (int mt = 0; mt < 4; mt++)
#pragma unroll
        for (int nt = 0; nt < 4; nt++)
#pragma unroll
            for (int r = 0; r < 4; r++) acc[mt][nt][r] = 0.f;

    const uint32_t bA = smem_u32(sA);
    const uint32_t bB = smem_u32(sB);
    const uint32_t rowA = ((wm * 64 + (lane & 15)) * SSTR + (lane >> 4) * 8) * 2;
    const uint32_t rowB = ((wn * 32 + (lane & 7)) * SSTR + ((lane >> 3) & 1) * 8) * 2;

#pragma unroll
    for (int ks = 0; ks < KS; ks++) {
        uint32_t ah[4][4], bh[4][2];
#pragma unroll
        for (int mt = 0; mt < 4; mt++) {
            uint32_t off = rowA + mt * (16 * SSTR * 2) + ks * 32;
            LDSM_X4(ah[mt][0], ah[mt][1], ah[mt][2], ah[mt][3], bA + off);
        }
#pragma unroll
        for (int nt = 0; nt < 4; nt++) {
            uint32_t off = rowB + nt * (8 * SSTR * 2) + ks * 32;
            LDSM_X2(bh[nt][0], bh[nt][1], bB + off);
        }
#pragma unroll
        for (int mt = 0; mt < 4; mt++)
#pragma unroll
            for (int nt = 0; nt < 4; nt++)
                MMA16816(acc[mt][nt], ah[mt], bh[nt]);
    }

    // ---------- epilogue ----------
    const int qid = lane >> 2;
    const int qt  = lane & 3;
#pragma unroll
    for (int mt = 0; mt < 4; mt++) {
        int m1 = wm * 64 + mt * 16 + qid;
        int m2 = m1 + 8;
        float bb1 = bias[o0 + m1], bb2 = bias[o0 + m2];
        float s1 = 0.f, q1 = 0.f, s2 = 0.f, q2 = 0.f;
        float mx1 = -3.4e38f, mx2 = -3.4e38f;
#pragma unroll
        for (int nt = 0; nt < 4; nt++) {
            float v0 = acc[mt][nt][0] + bb1, v1 = acc[mt][nt][1] + bb1;
            float v2 = acc[mt][nt][2] + bb2, v3 = acc[mt][nt][3] + bb2;
            if (!DOMAX) {
                int n = n0 + wn * 32 + nt * 8 + qt * 2;
                *(uint32_t*)&Y[(size_t)(o0 + m1) * NNc + n] = f22h(v0, v1);
                *(uint32_t*)&Y[(size_t)(o0 + m2) * NNc + n] = f22h(v2, v3);
            } else {
                mx1 = fmaxf(mx1, fmaxf(v0, v1));
                mx2 = fmaxf(mx2, fmaxf(v2, v3));
            }
            s1 += v0 + v1; q1 += v0 * v0 + v1 * v1;
            s2 += v2 + v3; q2 += v2 * v2 + v3 * v3;
        }
        s1 += __shfl_xor_sync(0xffffffffu, s1, 1); s1 += __shfl_xor_sync(0xffffffffu, s1, 2);
        q1 += __shfl_xor_sync(0xffffffffu, q1, 1); q1 += __shfl_xor_sync(0xffffffffu, q1, 2);
        s2 += __shfl_xor_sync(0xffffffffu, s2, 1); s2 += __shfl_xor_sync(0xffffffffu, s2, 2);
        q2 += __shfl_xor_sync(0xffffffffu, q2, 1); q2 += __shfl_xor_sync(0xffffffffu, q2, 2);
        if (DOMAX) {
            mx1 = fmaxf(mx1, __shfl_xor_sync(0xffffffffu, mx1, 1));
            mx1 = fmaxf(mx1, __shfl_xor_sync(0xffffffffu, mx1, 2));
            mx2 = fmaxf(mx2, __shfl_xor_sync(0xffffffffu, mx2, 1));
            mx2 = fmaxf(mx2, __shfl_xor_sync(0xffffffffu, mx2, 2));
            if (qt == 0) {
                int qidx = blockIdx.x * 4 + wn;     // warp tile N=32 == one query
                g_mx[(size_t)(o0 + m1) * NQ + qidx] = mx1;
                g_mx[(size_t)(o0 + m2) * NQ + qidx] = mx2;
            }
        }
        if (qt == 0) {
            atomicAdd(&s_sum[m1], s1); atomicAdd(&s_sq[m1], q1);
            atomicAdd(&s_sum[m2], s2); atomicAdd(&s_sq[m2], q2);
        }
    }
    __syncthreads();
    if (tid < 128) {
        g_ps[(size_t)(o0 + tid) * NCTA + blockIdx.x] = s_sum[tid];
        g_pq[(size_t)(o0 + tid) * NCTA + blockIdx.x] = s_sq[tid];
    }
}

// ---------------- kernel: reduce partials -> BN scale/shift ----------------
__global__ void k_reduce(const float* __restrict__ gam, const float* __restrict__ bet)
{
    __shared__ float ss[256], sq[256];
    int c = blockIdx.x, t = threadIdx.x;
    float s = g_ps[(size_t)c * NCTA + t]       + g_ps[(size_t)c * NCTA + 256 + t]
            + g_ps[(size_t)c * NCTA + 512 + t] + g_ps[(size_t)c * NCTA + 768 + t];
    float q = g_pq[(size_t)c * NCTA + t]       + g_pq[(size_t)c * NCTA + 256 + t]
            + g_pq[(size_t)c * NCTA + 512 + t] + g_pq[(size_t)c * NCTA + 768 + t];
    ss[t] = s; sq[t] = q;
    __syncthreads();
    for (int st = 128; st > 0; st >>= 1) {
        if (t < st) { ss[t] += ss[t + st]; sq[t] += sq[t + st]; }
        __syncthreads();
    }
    if (t == 0) {
        float mean = ss[0] * (1.f / NNc);
        float var  = sq[0] * (1.f / NNc) - mean * mean;
        float rs   = rsqrtf(var + EPSv);
        float sc   = gam[c] * rs;
        g_scale[c] = sc;
        g_shift[c] = fmaf(-mean, sc, bet[c]);
    }
}

// ---------------- kernel: BN3+ReLU applied to per-query max ----------------
__global__ void k_final(float* __restrict__ outf)
{
    int i = blockIdx.x * blockDim.x + threadIdx.x;   // 1048576
    int m = i & (Mq - 1);
    int o = (i >> 10) & 255;
    int b = i >> 18;
    float v = g_mx[(size_t)o * NQ + b * Mq + m];
    outf[((size_t)b * 256 + o) * Mq + m] = fmaxf(fmaf(g_scale[o], v, g_shift[o]), 0.f);
}

// ---------------- host launcher ----------------
extern "C" void kernel_launch(void* const* d_in, const int* in_sizes, int n_in,
                              void* d_out, int out_size)
{
    const float* pxyz = (const float*)d_in[0];
    const float* feat = (const float*)d_in[1];
    const int*   ind  = (const int*)d_in[2];
    const float* w1 = (const float*)d_in[3];  const float* b1 = (const float*)d_in[4];
    const float* g1 = (const float*)d_in[5];  const float* be1 = (const float*)d_in[6];
    const float* w2 = (const float*)d_in[7];  const float* b2 = (const float*)d_in[8];
    const float* g2 = (const float*)d_in[9];  const float* be2 = (const float*)d_in[10];
    const float* w3 = (const float*)d_in[11]; const float* b3 = (const float*)d_in[12];
    const float* g3 = (const float*)d_in[13]; const float* be3 = (const float*)d_in[14];

    float* out  = (float*)d_out;
    float* nxyz = out;
    float* fout = out + Bb * Mq * 3;

    float *pFT;
    __half *pWh, *pY1h, *pY2h;
    cudaGetSymbolAddress((void**)&pFT, g_featT);
    cudaGetSymbolAddress((void**)&pWh, g_Whf);
    cudaGetSymbolAddress((void**)&pY1h, g_Y1h);
    cudaGetSymbolAddress((void**)&pY2h, g_Y2h);

    const int DSM1 = 2 * 128 * (144 + 8) * 2;   // 77824 B (layer 1)
    const int DSM2 = 2 * 128 * (128 + 8) * 2;   // 69632 B (layers 2/3)
    cudaFuncSetAttribute(k_gemm_h<144,0,0>, cudaFuncAttributeMaxDynamicSharedMemorySize, DSM1);
    cudaFuncSetAttribute(k_gemm_h<128,1,0>, cudaFuncAttributeMaxDynamicSharedMemorySize, DSM2);
    cudaFuncSetAttribute(k_gemm_h<128,1,1>, cudaFuncAttributeMaxDynamicSharedMemorySize, DSM2);

    const int W2_OFF = KCP1 * 128;
    const int W3_OFF = KCP1 * 128 + 128 * 128;

    // launch 0: merged prep (newxyz + packW1/W2/W3)
    k_prep<<<528, 256>>>(pxyz, ind, w1, w2, w3, nxyz, pWh);
    // launch 1: ball query
    k_ballquery<<<(Bb * Mq * 32) / 256, 256>>>(pxyz, nxyz);
    // launch 2: feature transpose
    k_transpose<<<dim3(Np / 32, Cf / 32, Bb), dim3(32, 8)>>>(feat, pFT);

    // launch 3 (profiled slot): layer 1, one-shot K=144
    k_gemm_h<144,0,0><<<dim3(NCTA, 1), 256, DSM1>>>(pWh, b1, KCP1,
                                                    nullptr, pxyz, nxyz, pY1h);
    k_reduce<<<128, 256>>>(g1, be1);

    // layer 2: fused BN1+ReLU, one-shot K=128
    k_gemm_h<128,1,0><<<dim3(NCTA, 1), 256, DSM2>>>(pWh + W2_OFF, b2, 128,
                                                    pY1h, nullptr, nullptr, pY2h);
    k_reduce<<<128, 256>>>(g2, be2);

    // layer 3: fused BN2+ReLU, 256 out channels, max fused into epilogue (no Y3)
    k_gemm_h<128,1,1><<<dim3(NCTA, 2), 256, DSM2>>>(pWh + W3_OFF, b3, 128,
                                                    pY2h, nullptr, nullptr, nullptr);
    k_reduce<<<256, 256>>>(g3, be3);

    // BN3+ReLU on per-query maxima (4MB read, 4MB write)
    k_final<<<(Bb * 256 * Mq) / 256, 256>>>(fout);
}

// round 13
// speedup vs baseline: 1.3309x; 1.0376x over previous
#include <cuda_runtime.h>
#include <cuda_fp16.h>
#include <cstdint>
#include <cstddef>

// ---------------- problem constants ----------------
#define Bb   4
#define Np   16384
#define Cf   128
#define Mq   1024
#define Kq   32
#define NNc  131072            // Bb*Mq*Kq (GEMM column count)
#define R2c  0.16f
#define EPSv 1e-5f
#define KCP1 160               // layer1 W storage stride (compute uses 144)
#define NCTA 1024
#define NQ   4096              // total queries (B*M)

// ---------------- scratch (device globals) ----------------
__device__ int   g_idx[NNc];
__device__ __align__(16) __half g_Whf[KCP1*128 + 128*128 + 128*256];  // fp16 W, [o][cpad]
__device__ __align__(16) __half g_featTh[(size_t)Bb * Np * Cf];  // 16 MB (fp16, [b][n][c])
__device__ __align__(16) __half g_Y1h[(size_t)128 * NNc];        // 32 MB
__device__ __align__(16) __half g_Y2h[(size_t)128 * NNc];        // 32 MB
__device__ float g_mx[(size_t)256 * NQ];               // 4 MB  (layer3 raw max over K)
__device__ float g_ps[256 * NCTA];
__device__ float g_pq[256 * NCTA];
__device__ float g_scale[256];
__device__ float g_shift[256];

// ---------------- helpers ----------------
__device__ __forceinline__ uint32_t smem_u32(const void* p) {
    uint32_t a;
    asm("{ .reg .u64 t; cvta.to.shared.u64 t, %1; cvt.u32.u64 %0, t; }" : "=r"(a) : "l"(p));
    return a;
}
__device__ __forceinline__ uint32_t f22h(float lo, float hi) {
    uint32_t r;
    asm("cvt.rn.f16x2.f32 %0, %1, %2;" : "=r"(r) : "f"(hi), "f"(lo));
    return r;
}
#define CPASYNC16(dst, src) \
    asm volatile("cp.async.ca.shared.global [%0],[%1],16;" :: "r"(dst), "l"(src))
#define LDSM_X4(d0,d1,d2,d3,a) \
    asm volatile("ldmatrix.sync.aligned.m8n8.x4.shared.b16 {%0,%1,%2,%3},[%4];" \
                 : "=r"(d0),"=r"(d1),"=r"(d2),"=r"(d3) : "r"(a))
#define LDSM_X2(d0,d1,a) \
    asm volatile("ldmatrix.sync.aligned.m8n8.x2.shared.b16 {%0,%1},[%2];" \
                 : "=r"(d0),"=r"(d1) : "r"(a))
#define MMA16816(c, a, b) \
    asm volatile("mma.sync.aligned.m16n8k16.row.col.f32.f16.f16.f32 " \
                 "{%0,%1,%2,%3},{%4,%5,%6,%7},{%8,%9},{%0,%1,%2,%3};" \
                 : "+f"((c)[0]),"+f"((c)[1]),"+f"((c)[2]),"+f"((c)[3]) \
                 : "r"((a)[0]),"r"((a)[1]),"r"((a)[2]),"r"((a)[3]), \
                   "r"((b)[0]),"r"((b)[1]))

// ---------------- kernel: merged prep (newxyz gather + all weight packs) ----------------
__global__ void k_prep(const float* __restrict__ pxyz, const int* __restrict__ ind,
                       const float* __restrict__ W1, const float* __restrict__ W2,
                       const float* __restrict__ W3,
                       float* __restrict__ nxyz, __half* __restrict__ Wh)
{
    const int W2_OFF = KCP1 * 128;
    const int W3_OFF = KCP1 * 128 + 128 * 128;
    int blk = blockIdx.x, t = threadIdx.x;
    if (blk < 16) {
        int i = blk * 256 + t;
        int b = i >> 10;
        int n = ind[i];
        const float* p = pxyz + ((size_t)b * Np + n) * 3;
        nxyz[i * 3 + 0] = p[0];
        nxyz[i * 3 + 1] = p[1];
        nxyz[i * 3 + 2] = p[2];
    } else if (blk < 144) {
        int o = blk - 16, c = t;
        if (c < KCP1) {
            float v = 0.f;
            int oc = (c < 128) ? (c + 3) : ((c < 131) ? (c - 128) : -1);
            if (oc >= 0) v = W1[o * 131 + oc];
            Wh[o * KCP1 + c] = __float2half_rn(v);
        }
    } else if (blk < 272) {
        int o = blk - 144;
        if (t < 128) Wh[W2_OFF + o * 128 + t] = __float2half_rn(W2[o * 128 + t]);
    } else {
        int o = blk - 272;
        if (t < 128) Wh[W3_OFF + o * 128 + t] = __float2half_rn(W3[o * 128 + t]);
    }
}

// ---------------- kernel: ball query (warp per query) ----------------
__global__ void k_ballquery(const float* __restrict__ pxyz, const float* __restrict__ nxyz)
{
    int gtid = blockIdx.x * blockDim.x + threadIdx.x;
    int q    = gtid >> 5;
    int lane = gtid & 31;
    int b    = q >> 10;

    float nx = nxyz[q * 3 + 0], ny = nxyz[q * 3 + 1], nz = nxyz[q * 3 + 2];
    const float* px = pxyz + (size_t)b * Np * 3;

    int cnt = 0, first = 0;
    for (int n0 = 0; n0 < Np; n0 += 32) {
        int n = n0 + lane;
        float dx = px[n * 3 + 0] - nx, dy = px[n * 3 + 1] - ny, dz = px[n * 3 + 2] - nz;
        float d2 = __fadd_rn(__fadd_rn(__fmul_rn(dx, dx), __fmul_rn(dy, dy)), __fmul_rn(dz, dz));
        bool within = d2 < R2c;
        unsigned bal = __ballot_sync(0xffffffffu, within);
        if (bal) {
            if (cnt == 0) first = n0 + __ffs(bal) - 1;
            int pre = __popc(bal & ((1u << lane) - 1u));
            if (within && (cnt + pre) < Kq) g_idx[q * Kq + cnt + pre] = n;
            cnt += __popc(bal);
            if (cnt >= Kq) break;
        }
    }
    cnt = min(cnt, Kq);
    if (lane >= cnt) g_idx[q * Kq + lane] = first;
}

// ---------------- kernel: transpose features -> featTh[b][n][c] (fp16) ----------------
__global__ void k_transpose(const float* __restrict__ f, __half* __restrict__ ft)
{
    __shared__ float t[32][33];
    int b  = blockIdx.z;
    int n0 = blockIdx.x << 5, c0 = blockIdx.y << 5;
    int tx = threadIdx.x, ty = threadIdx.y;       // 32 x 8
#pragma unroll
    for (int i = 0; i < 32; i += 8)
        t[ty + i][tx] = f[((size_t)b * Cf + c0 + ty + i) * Np + n0 + tx];
    __syncthreads();
    // write fp16: thread tx handles channel pair (2*(tx&15), +1), rows split by tx>>4
#pragma unroll
    for (int i = 0; i < 32; i += 4) {
        int n  = n0 + (ty + (tx >> 4) * 8) + ((i >> 3) << 4);   // covers 32 rows in 4 iters? no:
        (void)n;
    }
    // simpler: each of 8 ty-iterations writes one row's 32 channels as 16 __half2
#pragma unroll
    for (int i = 0; i < 32; i += 8) {
        int n = n0 + ty + i;
        if (tx < 16) {
            __half2 v = __floats2half2_rn(t[tx * 2][ty + i], t[tx * 2 + 1][ty + i]);
            *(__half2*)&ft[((size_t)b * Np + n) * Cf + c0 + tx * 2] = v;
        }
    }
}

// ---------------- one-shot fused fp16 GEMM ----------------
// CTA: 128(M per split) x 128(N), FULL K in smem; 8 warps 2(M)x4(N).
// KH: K halves (144 layer1, 128 layers2/3). OSP: M-splits sharing one B tile.
// MODE 0: B row-gathered from fp16 featTh via cp.async + xyz tail (layer 1).
// MODE 1: B = relu(scale*Yprev + shift), Yprev fp16.
// DOMAX 1: no Y write; per-(row, query) max -> g_mx.
template <int KH, int MODE, int DOMAX, int OSP>
__global__ void __launch_bounds__(256, 2) k_gemm_h(
    const __half* __restrict__ Wh, const float* __restrict__ bias,
    int KCpad,
    const __half* __restrict__ Bsrc,
    const float* __restrict__ pxyz, const float* __restrict__ nxyz,
    __half* __restrict__ Y)
{
    constexpr int SSTR = KH + 8;         // row stride in halves
    constexpr int KHD8 = KH / 8;
    constexpr int KS   = KH / 16;
    extern __shared__ __half dsm[];      // [A0][A1 if OSP=2][B], each 128*SSTR halves
    __half* sB = dsm + OSP * 128 * SSTR;
    __shared__ float s_sum[128], s_sq[128];

    const int tid  = threadIdx.x;
    const int wid  = tid >> 5, lane = tid & 31;
    const int n0   = blockIdx.x << 7;
    const int wm   = wid >> 2;
    const int wn   = wid & 3;

    // ---------- stage A tiles (all OSP splits) via cp.async ----------
#pragma unroll
    for (int op = 0; op < OSP; op++) {
        uint32_t base = smem_u32(dsm + op * 128 * SSTR);
#pragma unroll
        for (int s = 0; s < (128 * KHD8) / 256; s++) {
            int i   = tid + s * 256;
            int row = i / KHD8;
            int seg = i - row * KHD8;
            const __half* src = Wh + (size_t)(op * 128 + row) * KCpad + seg * 8;
            CPASYNC16(base + (row * SSTR + seg * 8) * 2, src);
        }
    }

    // ---------- stage B tile ----------
    if (MODE == 0) {
        // channels 0..127: cp.async 16B row-gather from fp16 featTh
        uint32_t baseB = smem_u32(sB);
#pragma unroll
        for (int s = 0; s < 8; s++) {
            int i    = tid + (s << 8);
            int colL = i >> 4, seg = i & 15;
            int col  = n0 + colL;
            int idxv = g_idx[col];
            int b    = col >> 15;
            const __half* src = g_featTh + ((size_t)b * Np + idxv) * Cf + seg * 8;
            CPASYNC16(baseB + (colL * SSTR + seg * 8) * 2, src);
        }
        // tail channels 128..143: xyz diffs + zero pad
        if (tid < 128) {
            int col  = n0 + tid;
            int idxv = g_idx[col];
            int b    = col >> 15;
            int q    = col >> 5;
            const float* p  = &pxyz[((size_t)b * Np + idxv) * 3];
            float d0 = p[0] - nxyz[q * 3 + 0];
            float d1 = p[1] - nxyz[q * 3 + 1];
            float d2 = p[2] - nxyz[q * 3 + 2];
            uint4 u0; u0.x = f22h(d0, d1); u0.y = f22h(d2, 0.f); u0.z = 0u; u0.w = 0u;
            uint4 z = make_uint4(0u, 0u, 0u, 0u);
            *(uint4*)&sB[tid * SSTR + 128] = u0;
            *(uint4*)&sB[tid * SSTR + 136] = z;
        }
    } else {
#pragma unroll
        for (int s = 0; s < 16; s++) {
            int i   = tid + (s << 8);
            int col = i & 127;
            int cg0 = (i >> 7) << 2;
            int n   = n0 + col;
            float y0 = __half2float(Bsrc[(size_t)(cg0 + 0) * NNc + n]);
            float y1 = __half2float(Bsrc[(size_t)(cg0 + 1) * NNc + n]);
            float y2 = __half2float(Bsrc[(size_t)(cg0 + 2) * NNc + n]);
            float y3 = __half2float(Bsrc[(size_t)(cg0 + 3) * NNc + n]);
            float f0 = fmaxf(fmaf(g_scale[cg0 + 0], y0, g_shift[cg0 + 0]), 0.f);
            float f1 = fmaxf(fmaf(g_scale[cg0 + 1], y1, g_shift[cg0 + 1]), 0.f);
            float f2 = fmaxf(fmaf(g_scale[cg0 + 2], y2, g_shift[cg0 + 2]), 0.f);
            float f3 = fmaxf(fmaf(g_scale[cg0 + 3], y3, g_shift[cg0 + 3]), 0.f);
            *(uint2*)&sB[col * SSTR + cg0] = make_uint2(f22h(f0, f1), f22h(f2, f3));
        }
    }

    asm volatile("cp.async.wait_all;" ::: "memory");
    __syncthreads();

    const uint32_t bB = smem_u32(sB);
    const uint32_t rowAoff = ((wm * 64 + (lane & 15)) * SSTR + (lane >> 4) * 8) * 2;
    const uint32_t rowB    = ((wn * 32 + (lane & 7)) * SSTR + ((lane >> 3) & 1) * 8) * 2;
    const int qid = lane >> 2;
    const int qt  = lane & 3;

#pragma unroll
    for (int op = 0; op < OSP; op++) {
        const uint32_t bA = smem_u32(dsm + op * 128 * SSTR);
        const int o0 = op * 128;

        float acc[4][4][4];
#pragma unroll
        for (int mt = 0; mt < 4; mt++)
#pragma unroll
            for (int nt = 0; nt < 4; nt++)
#pragma unroll
                for (int r = 0; r < 4; r++) acc[mt][nt][r] = 0.f;

#pragma unroll
        for (int ks = 0; ks < KS; ks++) {
            uint32_t ah[4][4], bh[4][2];
#pragma unroll
            for (int mt = 0; mt < 4; mt++) {
                uint32_t off = rowAoff + mt * (16 * SSTR * 2) + ks * 32;
                LDSM_X4(ah[mt][0], ah[mt][1], ah[mt][2], ah[mt][3], bA + off);
            }
#pragma unroll
            for (int nt = 0; nt < 4; nt++) {
                uint32_t off = rowB + nt * (8 * SSTR * 2) + ks * 32;
                LDSM_X2(bh[nt][0], bh[nt][1], bB + off);
            }
#pragma unroll
            for (int mt = 0; mt < 4; mt++)
#pragma unroll
                for (int nt = 0; nt < 4; nt++)
                    MMA16816(acc[mt][nt], ah[mt], bh[nt]);
        }

        // ---------- epilogue for this M-split ----------
        if (OSP > 1) __syncthreads();              // prior split's g_ps writes done
        if (tid < 128) { s_sum[tid] = 0.f; s_sq[tid] = 0.f; }
        __syncthreads();

#pragma unroll
        for (int mt = 0; mt < 4; mt++) {
            int m1 = wm * 64 + mt * 16 + qid;
            int m2 = m1 + 8;
            float bb1 = bias[o0 + m1], bb2 = bias[o0 + m2];
            float s1 = 0.f, q1 = 0.f, s2 = 0.f, q2 = 0.f;
            float mx1 = -3.4e38f, mx2 = -3.4e38f;
#pragma unroll
            for (int nt = 0; nt < 4; nt++) {
                float v0 = acc[mt][nt][0] + bb1, v1 = acc[mt][nt][1] + bb1;
                float v2 = acc[mt][nt][2] + bb2, v3 = acc[mt][nt][3] + bb2;
                if (!DOMAX) {
                    int n = n0 + wn * 32 + nt * 8 + qt * 2;
                    *(uint32_t*)&Y[(size_t)(o0 + m1) * NNc + n] = f22h(v0, v1);
                    *(uint32_t*)&Y[(size_t)(o0 + m2) * NNc + n] = f22h(v2, v3);
                } else {
                    mx1 = fmaxf(mx1, fmaxf(v0, v1));
                    mx2 = fmaxf(mx2, fmaxf(v2, v3));
                }
                s1 += v0 + v1; q1 += v0 * v0 + v1 * v1;
                s2 += v2 + v3; q2 += v2 * v2 + v3 * v3;
            }
            s1 += __shfl_xor_sync(0xffffffffu, s1, 1); s1 += __shfl_xor_sync(0xffffffffu, s1, 2);
            q1 += __shfl_xor_sync(0xffffffffu, q1, 1); q1 += __shfl_xor_sync(0xffffffffu, q1, 2);
            s2 += __shfl_xor_sync(0xffffffffu, s2, 1); s2 += __shfl_xor_sync(0xffffffffu, s2, 2);
            q2 += __shfl_xor_sync(0xffffffffu, q2, 1); q2 += __shfl_xor_sync(0xffffffffu, q2, 2);
            if (DOMAX) {
                mx1 = fmaxf(mx1, __shfl_xor_sync(0xffffffffu, mx1, 1));
                mx1 = fmaxf(mx1, __shfl_xor_sync(0xffffffffu, mx1, 2));
                mx2 = fmaxf(mx2, __shfl_xor_sync(0xffffffffu, mx2, 1));
                mx2 = fmaxf(mx2, __shfl_xor_sync(0xffffffffu, mx2, 2));
                if (qt == 0) {
                    int qidx = blockIdx.x * 4 + wn;
                    g_mx[(size_t)(o0 + m1) * NQ + qidx] = mx1;
                    g_mx[(size_t)(o0 + m2) * NQ + qidx] = mx2;
                }
            }
            if (qt == 0) {
                atomicAdd(&s_sum[m1], s1); atomicAdd(&s_sq[m1], q1);
                atomicAdd(&s_sum[m2], s2); atomicAdd(&s_sq[m2], q2);
            }
        }
        __syncthreads();
        if (tid < 128) {
            g_ps[(size_t)(o0 + tid) * NCTA + blockIdx.x] = s_sum[tid];
            g_pq[(size_t)(o0 + tid) * NCTA + blockIdx.x] = s_sq[tid];
        }
    }
}

// ---------------- kernel: reduce partials -> BN scale/shift ----------------
__global__ void k_reduce(const float* __restrict__ gam, const float* __restrict__ bet)
{
    __shared__ float ss[256], sq[256];
    int c = blockIdx.x, t = threadIdx.x;
    float s = g_ps[(size_t)c * NCTA + t]       + g_ps[(size_t)c * NCTA + 256 + t]
            + g_ps[(size_t)c * NCTA + 512 + t] + g_ps[(size_t)c * NCTA + 768 + t];
    float q = g_pq[(size_t)c * NCTA + t]       + g_pq[(size_t)c * NCTA + 256 + t]
            + g_pq[(size_t)c * NCTA + 512 + t] + g_pq[(size_t)c * NCTA + 768 + t];
    ss[t] = s; sq[t] = q;
    __syncthreads();
    for (int st = 128; st > 0; st >>= 1) {
        if (t < st) { ss[t] += ss[t + st]; sq[t] += sq[t + st]; }
        __syncthreads();
    }
    if (t == 0) {
        float mean = ss[0] * (1.f / NNc);
        float var  = sq[0] * (1.f / NNc) - mean * mean;
        float rs   = rsqrtf(var + EPSv);
        float sc   = gam[c] * rs;
        g_scale[c] = sc;
        g_shift[c] = fmaf(-mean, sc, bet[c]);
    }
}

// ---------------- kernel: BN3+ReLU applied to per-query max ----------------
__global__ void k_final(float* __restrict__ outf)
{
    int i = blockIdx.x * blockDim.x + threadIdx.x;   // 1048576
    int m = i & (Mq - 1);
    int o = (i >> 10) & 255;
    int b = i >> 18;
    float v = g_mx[(size_t)o * NQ + b * Mq + m];
    outf[((size_t)b * 256 + o) * Mq + m] = fmaxf(fmaf(g_scale[o], v, g_shift[o]), 0.f);
}

// ---------------- host launcher ----------------
extern "C" void kernel_launch(void* const* d_in, const int* in_sizes, int n_in,
                              void* d_out, int out_size)
{
    const float* pxyz = (const float*)d_in[0];
    const float* feat = (const float*)d_in[1];
    const int*   ind  = (const int*)d_in[2];
    const float* w1 = (const float*)d_in[3];  const float* b1 = (const float*)d_in[4];
    const float* g1 = (const float*)d_in[5];  const float* be1 = (const float*)d_in[6];
    const float* w2 = (const float*)d_in[7];  const float* b2 = (const float*)d_in[8];
    const float* g2 = (const float*)d_in[9];  const float* be2 = (const float*)d_in[10];
    const float* w3 = (const float*)d_in[11]; const float* b3 = (const float*)d_in[12];
    const float* g3 = (const float*)d_in[13]; const float* be3 = (const float*)d_in[14];

    float* out  = (float*)d_out;
    float* nxyz = out;
    float* fout = out + Bb * Mq * 3;

    __half *pWh, *pY1h, *pY2h, *pFTh;
    cudaGetSymbolAddress((void**)&pWh, g_Whf);
    cudaGetSymbolAddress((void**)&pY1h, g_Y1h);
    cudaGetSymbolAddress((void**)&pY2h, g_Y2h);
    cudaGetSymbolAddress((void**)&pFTh, g_featTh);

    const int DSM1 = 2 * 128 * (144 + 8) * 2;   // 77824 B (layer 1: A + B)
    const int DSM2 = 2 * 128 * (128 + 8) * 2;   // 69632 B (layer 2: A + B)
    const int DSM3 = 3 * 128 * (128 + 8) * 2;   // 104448 B (layer 3: A0 + A1 + B)
    cudaFuncSetAttribute(k_gemm_h<144,0,0,1>, cudaFuncAttributeMaxDynamicSharedMemorySize, DSM1);
    cudaFuncSetAttribute(k_gemm_h<128,1,0,1>, cudaFuncAttributeMaxDynamicSharedMemorySize, DSM2);
    cudaFuncSetAttribute(k_gemm_h<128,1,1,2>, cudaFuncAttributeMaxDynamicSharedMemorySize, DSM3);

    const int W2_OFF = KCP1 * 128;
    const int W3_OFF = KCP1 * 128 + 128 * 128;

    // launch 0: merged prep (newxyz + packW1/W2/W3)
    k_prep<<<528, 256>>>(pxyz, ind, w1, w2, w3, nxyz, pWh);
    // launch 1: ball query
    k_ballquery<<<(Bb * Mq * 32) / 256, 256>>>(pxyz, nxyz);
    // launch 2: feature transpose (fp16 out)
    k_transpose<<<dim3(Np / 32, Cf / 32, Bb), dim3(32, 8)>>>(feat, pFTh);

    // launch 3 (profiled slot): layer 1, one-shot K=144, cp.async gather
    k_gemm_h<144,0,0,1><<<NCTA, 256, DSM1>>>(pWh, b1, KCP1,
                                             nullptr, pxyz, nxyz, pY1h);
    k_reduce<<<128, 256>>>(g1, be1);

    // layer 2: fused BN1+ReLU, one-shot K=128
    k_gemm_h<128,1,0,1><<<NCTA, 256, DSM2>>>(pWh + W2_OFF, b2, 128,
                                             pY1h, nullptr, nullptr, pY2h);
    k_reduce<<<128, 256>>>(g2, be2);

    // layer 3: fused BN2+ReLU, both M-halves share one B tile (OSP=2), max fused
    k_gemm_h<128,1,1,2><<<NCTA, 256, DSM3>>>(pWh + W3_OFF, b3, 128,
                                             pY2h, nullptr, nullptr, nullptr);
    k_reduce<<<256, 256>>>(g3, be3);

    // BN3+ReLU on per-query maxima (4MB read, 4MB write)
    k_final<<<(Bb * 256 * Mq) / 256, 256>>>(fout);
}